// round 1
// baseline (speedup 1.0000x reference)
#include <cuda_runtime.h>
#include <math.h>

#define NN      32768      // nodes
#define GG      128        // graphs
#define NPG     256        // nodes per graph
#define HID     128
#define NH      8
#define DH      16
#define EE      1048576    // edges
#define NLAYERS 3

// ---------------- scratch (device globals; no runtime alloc allowed) ----------------
__device__ float g_h  [NN * HID];
__device__ float g_h2 [NN * HID];
__device__ float g_tmp[NN * HID];
__device__ float g_q  [NN * HID];
__device__ float g_k  [NN * HID];
__device__ float g_v  [NN * HID];
__device__ float g_pooled[GG * 3 * HID];
__device__ int   g_deg[NN];
__device__ int   g_rp [NN + 1];
__device__ int   g_cur[NN];
__device__ int   g_col[EE];
__device__ float g_dis[NN];

// ---------------- helpers ----------------
// LayerNorm over 128 features, blockDim.x == 128. sh must hold >= 8 floats.
__device__ __forceinline__ float block_ln_128(float v, float gamma, float beta, float* sh) {
    float s = v, s2 = v * v;
    #pragma unroll
    for (int o = 16; o > 0; o >>= 1) {
        s  += __shfl_down_sync(0xffffffffu, s,  o);
        s2 += __shfl_down_sync(0xffffffffu, s2, o);
    }
    int w = threadIdx.x >> 5, l = threadIdx.x & 31;
    if (l == 0) { sh[w] = s; sh[4 + w] = s2; }
    __syncthreads();
    float ts  = sh[0] + sh[1] + sh[2] + sh[3];
    float ts2 = sh[4] + sh[5] + sh[6] + sh[7];
    float m   = ts  * (1.0f / 128.0f);
    float var = ts2 * (1.0f / 128.0f) - m * m;
    float r   = rsqrtf(var + 1e-5f);
    __syncthreads();  // sh reusable after
    return (v - m) * r * gamma + beta;
}

// ---------------- CSR build ----------------
__global__ void k_hist(const int* __restrict__ dst, int* __restrict__ deg) {
    int e = blockIdx.x * blockDim.x + threadIdx.x;
    if (e < EE) atomicAdd(&deg[dst[e]], 1);
}

__global__ void k_scan(const int* __restrict__ deg, int* __restrict__ rp, int* __restrict__ cur) {
    __shared__ int part[1024];
    int tid = threadIdx.x;            // 1024 threads
    int base = tid * 32;
    int v[32];
    int s = 0;
    #pragma unroll
    for (int i = 0; i < 32; i++) { v[i] = deg[base + i]; s += v[i]; }
    part[tid] = s;
    __syncthreads();
    for (int off = 1; off < 1024; off <<= 1) {
        int t = (tid >= off) ? part[tid - off] : 0;
        __syncthreads();
        part[tid] += t;
        __syncthreads();
    }
    int run = part[tid] - s;          // exclusive prefix
    #pragma unroll
    for (int i = 0; i < 32; i++) {
        rp[base + i]  = run;
        cur[base + i] = run;
        run += v[i];
    }
    if (tid == 1023) rp[NN] = run;
}

__global__ void k_dis(const int* __restrict__ deg, float* __restrict__ dis) {
    int n = blockIdx.x * blockDim.x + threadIdx.x;
    if (n < NN) dis[n] = rsqrtf((float)deg[n] + 1.0f);   // +1 self loop
}

__global__ void k_fill(const int* __restrict__ src, const int* __restrict__ dst,
                       int* __restrict__ cur, int* __restrict__ col) {
    int e = blockIdx.x * blockDim.x + threadIdx.x;
    if (e < EE) {
        int d = dst[e];
        int pos = atomicAdd(&cur[d], 1);
        col[pos] = src[e];
    }
}

// ---------------- input projection: relu(ln(x @ W_in + b_in)) ----------------
__global__ void k_input_proj(const float* __restrict__ x, const float* __restrict__ W,
                             const float* __restrict__ b, const float* __restrict__ g,
                             const float* __restrict__ be, float* __restrict__ out) {
    int n = blockIdx.x, f = threadIdx.x;
    __shared__ float xs[16];
    __shared__ float red[8];
    if (f < 15) xs[f] = x[n * 15 + f];
    __syncthreads();
    float acc = b[f];
    #pragma unroll
    for (int k = 0; k < 15; k++) acc = fmaf(xs[k], W[k * 128 + f], acc);
    float y = block_ln_128(acc, g[f], be[f], red);
    out[n * 128 + f] = fmaxf(y, 0.0f);
}

// ---------------- tiled SGEMM: C[M,128] = A[M,128] @ op(B[128,128]) (+bias) ----------------
// TRANSB=0: C[n,f] = sum_k A[n,k] * B[k,f]
// TRANSB=1: C[n,f] = sum_k A[n,k] * B[f,k]
template <int TRANSB, int BIAS>
__global__ __launch_bounds__(256) void k_gemm128(const float* __restrict__ A,
                                                 const float* __restrict__ B,
                                                 const float* __restrict__ bias,
                                                 float* __restrict__ C) {
    __shared__ float As[64 * 32];
    __shared__ float Bs[32 * 132];
    const int t = threadIdx.x;
    const int warp = t >> 5, lane = t & 31;
    const int row0 = blockIdx.x * 64;

    float acc[8][4];
    #pragma unroll
    for (int i = 0; i < 8; i++)
        #pragma unroll
        for (int j = 0; j < 4; j++) acc[i][j] = 0.0f;

    for (int kt = 0; kt < 4; kt++) {
        const int k0 = kt * 32;
        // load A tile 64x32
        {
            int r = t >> 2, kk = (t & 3) * 8;
            float4 a0 = *(const float4*)&A[(row0 + r) * 128 + k0 + kk];
            float4 a1 = *(const float4*)&A[(row0 + r) * 128 + k0 + kk + 4];
            *(float4*)&As[r * 32 + kk]     = a0;
            *(float4*)&As[r * 32 + kk + 4] = a1;
        }
        // load B tile 32x128 (padded stride 132)
        if (TRANSB) {
            int c = t >> 1, kk0 = (t & 1) * 16;
            #pragma unroll
            for (int qd = 0; qd < 4; qd++) {
                float4 v4 = *(const float4*)&B[c * 128 + k0 + kk0 + qd * 4];
                Bs[(kk0 + qd * 4 + 0) * 132 + c] = v4.x;
                Bs[(kk0 + qd * 4 + 1) * 132 + c] = v4.y;
                Bs[(kk0 + qd * 4 + 2) * 132 + c] = v4.z;
                Bs[(kk0 + qd * 4 + 3) * 132 + c] = v4.w;
            }
        } else {
            #pragma unroll
            for (int qd = 0; qd < 4; qd++) {
                int idx = qd * 1024 + t * 4;
                int k = idx >> 7, c = idx & 127;
                float4 v4 = *(const float4*)&B[(k0 + k) * 128 + c];
                *(float4*)&Bs[k * 132 + c] = v4;
            }
        }
        __syncthreads();
        #pragma unroll
        for (int k = 0; k < 32; k++) {
            float4 bv = *(const float4*)&Bs[k * 132 + lane * 4];
            #pragma unroll
            for (int i = 0; i < 8; i++) {
                float a = As[(warp * 8 + i) * 32 + k];
                acc[i][0] = fmaf(a, bv.x, acc[i][0]);
                acc[i][1] = fmaf(a, bv.y, acc[i][1]);
                acc[i][2] = fmaf(a, bv.z, acc[i][2]);
                acc[i][3] = fmaf(a, bv.w, acc[i][3]);
            }
        }
        __syncthreads();
    }

    float4 bb = make_float4(0.f, 0.f, 0.f, 0.f);
    if (BIAS) bb = *(const float4*)&bias[lane * 4];
    #pragma unroll
    for (int i = 0; i < 8; i++) {
        int r = row0 + warp * 8 + i;
        float4 o;
        o.x = acc[i][0] + bb.x; o.y = acc[i][1] + bb.y;
        o.z = acc[i][2] + bb.z; o.w = acc[i][3] + bb.w;
        *(float4*)&C[r * 128 + lane * 4] = o;
    }
}

// ---------------- GCN aggregate + bias + LN + relu + residual ----------------
__global__ void k_gcn_agg(const float* __restrict__ hw, const float* __restrict__ hin,
                          const int* __restrict__ rp, const int* __restrict__ col,
                          const float* __restrict__ dis,
                          const float* __restrict__ bc, const float* __restrict__ gn,
                          const float* __restrict__ bn, float* __restrict__ hout,
                          int residual) {
    int n = blockIdx.x, f = threadIdx.x;
    __shared__ float red[8];
    float dn = dis[n];
    float acc = dn * hw[n * 128 + f];   // self loop (dis[d]*hw[d]); outer dis[d] applied later
    int beg = rp[n], end = rp[n + 1];
    int e = beg;
    for (; e + 4 <= end; e += 4) {
        int s0 = __ldg(&col[e]),     s1 = __ldg(&col[e + 1]);
        int s2 = __ldg(&col[e + 2]), s3 = __ldg(&col[e + 3]);
        float w0 = __ldg(&dis[s0]), w1 = __ldg(&dis[s1]);
        float w2 = __ldg(&dis[s2]), w3 = __ldg(&dis[s3]);
        float v0 = hw[s0 * 128 + f], v1 = hw[s1 * 128 + f];
        float v2 = hw[s2 * 128 + f], v3 = hw[s3 * 128 + f];
        acc = fmaf(w0, v0, acc); acc = fmaf(w1, v1, acc);
        acc = fmaf(w2, v2, acc); acc = fmaf(w3, v3, acc);
    }
    for (; e < end; e++) {
        int s = __ldg(&col[e]);
        acc = fmaf(__ldg(&dis[s]), hw[s * 128 + f], acc);
    }
    float val = fmaf(dn, acc, bc[f]);
    float y = fmaxf(block_ln_128(val, gn[f], bn[f], red), 0.0f);
    if (residual) y += hin[n * 128 + f];
    hout[n * 128 + f] = y;
}

// ---------------- attention: one block per (graph, head) ----------------
__global__ __launch_bounds__(256) void k_attn(const float* __restrict__ q,
                                              const float* __restrict__ k,
                                              const float* __restrict__ v,
                                              float* __restrict__ o) {
    int g = blockIdx.x >> 3;
    int h = blockIdx.x & 7;
    int t = threadIdx.x;          // query index within graph, 0..255
    __shared__ float Ks[256][16];
    __shared__ float Vs[256][16];
    const long base = (long)(g * NPG) * 128 + h * 16;

    {
        const float4* kp = (const float4*)(k + base + (long)t * 128);
        const float4* vp = (const float4*)(v + base + (long)t * 128);
        *(float4*)&Ks[t][0]  = kp[0]; *(float4*)&Ks[t][4]  = kp[1];
        *(float4*)&Ks[t][8]  = kp[2]; *(float4*)&Ks[t][12] = kp[3];
        *(float4*)&Vs[t][0]  = vp[0]; *(float4*)&Vs[t][4]  = vp[1];
        *(float4*)&Vs[t][8]  = vp[2]; *(float4*)&Vs[t][12] = vp[3];
    }
    float qr[16];
    {
        const float4* qp = (const float4*)(q + base + (long)t * 128);
        float4 a = qp[0], b = qp[1], c = qp[2], d = qp[3];
        qr[0]=a.x; qr[1]=a.y; qr[2]=a.z; qr[3]=a.w;
        qr[4]=b.x; qr[5]=b.y; qr[6]=b.z; qr[7]=b.w;
        qr[8]=c.x; qr[9]=c.y; qr[10]=c.z; qr[11]=c.w;
        qr[12]=d.x; qr[13]=d.y; qr[14]=d.z; qr[15]=d.w;
    }
    __syncthreads();

    float m = -1e30f, l = 0.0f;
    float acc[16];
    #pragma unroll
    for (int d = 0; d < 16; d++) acc[d] = 0.0f;

    for (int j = 0; j < 256; j++) {
        float4 k0 = *(const float4*)&Ks[j][0];
        float4 k1 = *(const float4*)&Ks[j][4];
        float4 k2 = *(const float4*)&Ks[j][8];
        float4 k3 = *(const float4*)&Ks[j][12];
        float s = qr[0]*k0.x + qr[1]*k0.y + qr[2]*k0.z + qr[3]*k0.w
                + qr[4]*k1.x + qr[5]*k1.y + qr[6]*k1.z + qr[7]*k1.w
                + qr[8]*k2.x + qr[9]*k2.y + qr[10]*k2.z + qr[11]*k2.w
                + qr[12]*k3.x + qr[13]*k3.y + qr[14]*k3.z + qr[15]*k3.w;
        s *= 0.25f;
        float mn = fmaxf(m, s);
        float c1 = __expf(m - mn);
        float p  = __expf(s - mn);
        l = l * c1 + p;
        float4 v0 = *(const float4*)&Vs[j][0];
        float4 v1 = *(const float4*)&Vs[j][4];
        float4 v2 = *(const float4*)&Vs[j][8];
        float4 v3 = *(const float4*)&Vs[j][12];
        acc[0]  = acc[0]  * c1 + p * v0.x; acc[1]  = acc[1]  * c1 + p * v0.y;
        acc[2]  = acc[2]  * c1 + p * v0.z; acc[3]  = acc[3]  * c1 + p * v0.w;
        acc[4]  = acc[4]  * c1 + p * v1.x; acc[5]  = acc[5]  * c1 + p * v1.y;
        acc[6]  = acc[6]  * c1 + p * v1.z; acc[7]  = acc[7]  * c1 + p * v1.w;
        acc[8]  = acc[8]  * c1 + p * v2.x; acc[9]  = acc[9]  * c1 + p * v2.y;
        acc[10] = acc[10] * c1 + p * v2.z; acc[11] = acc[11] * c1 + p * v2.w;
        acc[12] = acc[12] * c1 + p * v3.x; acc[13] = acc[13] * c1 + p * v3.y;
        acc[14] = acc[14] * c1 + p * v3.z; acc[15] = acc[15] * c1 + p * v3.w;
        m = mn;
    }
    float inv = 1.0f / l;
    float4 o0 = make_float4(acc[0]*inv,  acc[1]*inv,  acc[2]*inv,  acc[3]*inv);
    float4 o1 = make_float4(acc[4]*inv,  acc[5]*inv,  acc[6]*inv,  acc[7]*inv);
    float4 o2 = make_float4(acc[8]*inv,  acc[9]*inv,  acc[10]*inv, acc[11]*inv);
    float4 o3 = make_float4(acc[12]*inv, acc[13]*inv, acc[14]*inv, acc[15]*inv);
    float4* op = (float4*)(o + base + (long)t * 128);
    op[0] = o0; op[1] = o1; op[2] = o2; op[3] = o3;
}

// ---------------- out-proj residual LN ----------------
__global__ void k_ln_res(const float* __restrict__ o2, const float* __restrict__ hres,
                         const float* __restrict__ ga, const float* __restrict__ ba,
                         float* __restrict__ out) {
    int n = blockIdx.x, f = threadIdx.x;
    __shared__ float red[8];
    float v = o2[n * 128 + f] + hres[n * 128 + f];
    out[n * 128 + f] = block_ln_128(v, ga[f], ba[f], red);
}

// ---------------- pooling: [mean, max, sum] per graph ----------------
__global__ void k_pool(const float* __restrict__ h, float* __restrict__ pooled) {
    int g = blockIdx.x, f = threadIdx.x;
    float s = 0.0f, mx = -1e30f;
    const float* p = h + (long)(g * NPG) * 128 + f;
    for (int j = 0; j < NPG; j++) {
        float v = p[j * 128];
        s += v;
        mx = fmaxf(mx, v);
    }
    pooled[g * 384 + f]       = s * (1.0f / 256.0f);
    pooled[g * 384 + 128 + f] = mx;
    pooled[g * 384 + 256 + f] = s;
}

// ---------------- classifier ----------------
__global__ void k_classifier(const float* __restrict__ pooled,
                             const float* __restrict__ W1, const float* __restrict__ b1,
                             const float* __restrict__ g1, const float* __restrict__ beta1,
                             const float* __restrict__ W2, const float* __restrict__ b2,
                             const float* __restrict__ W3, const float* __restrict__ b3,
                             float* __restrict__ out) {
    int g = blockIdx.x, f = threadIdx.x;
    __shared__ float ps[384];
    __shared__ float z1[128];
    __shared__ float z2[64];
    __shared__ float red[8];
    for (int i = f; i < 384; i += 128) ps[i] = pooled[g * 384 + i];
    __syncthreads();
    float acc = b1[f];
    for (int k = 0; k < 384; k++) acc = fmaf(ps[k], W1[k * 128 + f], acc);
    float y = fmaxf(block_ln_128(acc, g1[f], beta1[f], red), 0.0f);
    z1[f] = y;
    __syncthreads();
    if (f < 64) {
        float a = b2[f];
        #pragma unroll 8
        for (int k = 0; k < 128; k++) a = fmaf(z1[k], W2[k * 64 + f], a);
        z2[f] = fmaxf(a, 0.0f);
    }
    __syncthreads();
    if (f < 2) {
        float a = b3[f];
        #pragma unroll
        for (int k = 0; k < 64; k++) a = fmaf(z2[k], W3[k * 2 + f], a);
        out[g * 2 + f] = a;
    }
}

// ---------------- launch ----------------
extern "C" void kernel_launch(void* const* d_in, const int* in_sizes, int n_in,
                              void* d_out, int out_size) {
    const float* x     = (const float*)d_in[0];
    const int*   ei    = (const int*)  d_in[1];
    // d_in[2] = batch (unused; graphs are equal-sized)
    const float* W_in  = (const float*)d_in[3];
    const float* b_in  = (const float*)d_in[4];
    const float* g_in  = (const float*)d_in[5];
    const float* be_in = (const float*)d_in[6];
    const float* Wc    = (const float*)d_in[7];
    const float* bc    = (const float*)d_in[8];
    const float* gn    = (const float*)d_in[9];
    const float* bn    = (const float*)d_in[10];
    const float* Wq    = (const float*)d_in[11];
    const float* bq    = (const float*)d_in[12];
    const float* Wk    = (const float*)d_in[13];
    const float* bk    = (const float*)d_in[14];
    const float* Wv    = (const float*)d_in[15];
    const float* bv    = (const float*)d_in[16];
    const float* Wo    = (const float*)d_in[17];
    const float* bo    = (const float*)d_in[18];
    const float* ga    = (const float*)d_in[19];
    const float* ba    = (const float*)d_in[20];
    const float* W1    = (const float*)d_in[21];
    const float* b1    = (const float*)d_in[22];
    const float* g1    = (const float*)d_in[23];
    const float* beta1 = (const float*)d_in[24];
    const float* W2    = (const float*)d_in[25];
    const float* b2    = (const float*)d_in[26];
    const float* W3    = (const float*)d_in[27];
    const float* b3    = (const float*)d_in[28];
    float* out = (float*)d_out;

    const int* src = ei;
    const int* dst = ei + EE;

    float *p_h, *p_h2, *p_tmp, *p_q, *p_k, *p_v, *p_pool, *p_dis;
    int *p_deg, *p_rp, *p_cur, *p_col;
    cudaGetSymbolAddress((void**)&p_h,   g_h);
    cudaGetSymbolAddress((void**)&p_h2,  g_h2);
    cudaGetSymbolAddress((void**)&p_tmp, g_tmp);
    cudaGetSymbolAddress((void**)&p_q,   g_q);
    cudaGetSymbolAddress((void**)&p_k,   g_k);
    cudaGetSymbolAddress((void**)&p_v,   g_v);
    cudaGetSymbolAddress((void**)&p_pool,g_pooled);
    cudaGetSymbolAddress((void**)&p_deg, g_deg);
    cudaGetSymbolAddress((void**)&p_rp,  g_rp);
    cudaGetSymbolAddress((void**)&p_cur, g_cur);
    cudaGetSymbolAddress((void**)&p_col, g_col);
    cudaGetSymbolAddress((void**)&p_dis, g_dis);

    // --- CSR build (per launch; no caching allowed) ---
    cudaMemsetAsync(p_deg, 0, NN * sizeof(int));
    k_hist<<<EE / 256, 256>>>(dst, p_deg);
    k_scan<<<1, 1024>>>(p_deg, p_rp, p_cur);
    k_dis<<<NN / 256, 256>>>(p_deg, p_dis);
    k_fill<<<EE / 256, 256>>>(src, dst, p_cur, p_col);

    // --- input projection ---
    k_input_proj<<<NN, 128>>>(x, W_in, b_in, g_in, be_in, p_h);

    // --- 3 GCN layers (ping-pong h buffers) ---
    float* cur = p_h;
    float* nxt = p_h2;
    for (int i = 0; i < NLAYERS; i++) {
        k_gemm128<0, 0><<<NN / 64, 256>>>(cur, Wc + i * HID * HID, nullptr, p_tmp);
        k_gcn_agg<<<NN, 128>>>(p_tmp, cur, p_rp, p_col, p_dis,
                               bc + i * HID, gn + i * HID, bn + i * HID, nxt, i > 0);
        float* t = cur; cur = nxt; nxt = t;
    }
    // after 3 layers: cur == p_h2

    // --- MHA ---
    k_gemm128<1, 1><<<NN / 64, 256>>>(cur, Wq, bq, p_q);
    k_gemm128<1, 1><<<NN / 64, 256>>>(cur, Wk, bk, p_k);
    k_gemm128<1, 1><<<NN / 64, 256>>>(cur, Wv, bv, p_v);
    k_attn<<<GG * NH, 256>>>(p_q, p_k, p_v, p_tmp);
    k_gemm128<1, 1><<<NN / 64, 256>>>(p_tmp, Wo, bo, p_q);   // p_q free, reuse
    k_ln_res<<<NN, 128>>>(p_q, cur, ga, ba, nxt);            // nxt == p_h, free

    // --- pooling + classifier ---
    k_pool<<<GG, 128>>>(nxt, p_pool);
    k_classifier<<<GG, 128>>>(p_pool, W1, b1, g1, beta1, W2, b2, W3, b3, out);
}

// round 2
// speedup vs baseline: 1.2764x; 1.2764x over previous
#include <cuda_runtime.h>
#include <math.h>

#define NN      32768      // nodes
#define GG      128        // graphs
#define NPG     256        // nodes per graph
#define HID     128
#define NH      8
#define DH      16
#define EE      1048576    // edges
#define NLAYERS 3

typedef unsigned long long ull;

// ---------------- packed f32x2 helpers ----------------
__device__ __forceinline__ ull pk2(float lo, float hi) {
    ull r; asm("mov.b64 %0,{%1,%2};" : "=l"(r) : "f"(lo), "f"(hi)); return r;
}
__device__ __forceinline__ void up2(ull v, float& lo, float& hi) {
    asm("mov.b64 {%0,%1},%2;" : "=f"(lo), "=f"(hi) : "l"(v));
}
__device__ __forceinline__ ull fma2(ull a, ull b, ull c) {
    ull d; asm("fma.rn.f32x2 %0,%1,%2,%3;" : "=l"(d) : "l"(a), "l"(b), "l"(c)); return d;
}

// ---------------- scratch (device globals; no runtime alloc allowed) ----------------
__device__ float g_h  [NN * HID];
__device__ float g_h2 [NN * HID];
__device__ float g_tmp[NN * HID];
__device__ float g_q  [NN * HID];
__device__ float g_k  [NN * HID];
__device__ float g_v  [NN * HID];
__device__ float g_pooled[GG * 3 * HID];
__device__ int   g_deg[NN];
__device__ int   g_rp [NN + 1];
__device__ int   g_cur[NN];
__device__ int   g_col[EE];
__device__ float g_dis[NN];

// ---------------- helpers ----------------
// LayerNorm over 128 features, blockDim.x == 128. sh must hold >= 8 floats.
__device__ __forceinline__ float block_ln_128(float v, float gamma, float beta, float* sh) {
    float s = v, s2 = v * v;
    #pragma unroll
    for (int o = 16; o > 0; o >>= 1) {
        s  += __shfl_down_sync(0xffffffffu, s,  o);
        s2 += __shfl_down_sync(0xffffffffu, s2, o);
    }
    int w = threadIdx.x >> 5, l = threadIdx.x & 31;
    if (l == 0) { sh[w] = s; sh[4 + w] = s2; }
    __syncthreads();
    float ts  = sh[0] + sh[1] + sh[2] + sh[3];
    float ts2 = sh[4] + sh[5] + sh[6] + sh[7];
    float m   = ts  * (1.0f / 128.0f);
    float var = ts2 * (1.0f / 128.0f) - m * m;
    float r   = rsqrtf(var + 1e-5f);
    __syncthreads();
    return (v - m) * r * gamma + beta;
}

// ---------------- CSR build ----------------
__global__ void k_hist(const int* __restrict__ dst, int* __restrict__ deg) {
    int e = blockIdx.x * blockDim.x + threadIdx.x;
    if (e < EE) atomicAdd(&deg[dst[e]], 1);
}

__global__ void k_scan(const int* __restrict__ deg, int* __restrict__ rp,
                       int* __restrict__ cur, float* __restrict__ dis) {
    __shared__ int part[1024];
    int tid = threadIdx.x;            // 1024 threads
    int base = tid * 32;
    int v[32];
    int s = 0;
    #pragma unroll
    for (int i = 0; i < 32; i++) { v[i] = deg[base + i]; s += v[i]; }
    part[tid] = s;
    __syncthreads();
    for (int off = 1; off < 1024; off <<= 1) {
        int t = (tid >= off) ? part[tid - off] : 0;
        __syncthreads();
        part[tid] += t;
        __syncthreads();
    }
    int run = part[tid] - s;          // exclusive prefix
    #pragma unroll
    for (int i = 0; i < 32; i++) {
        rp[base + i]  = run;
        cur[base + i] = run;
        dis[base + i] = rsqrtf((float)v[i] + 1.0f);  // +1 self loop
        run += v[i];
    }
    if (tid == 1023) rp[NN] = run;
}

__global__ void k_fill(const int* __restrict__ src, const int* __restrict__ dst,
                       int* __restrict__ cur, int* __restrict__ col) {
    int e = blockIdx.x * blockDim.x + threadIdx.x;
    if (e < EE) {
        int d = dst[e];
        int pos = atomicAdd(&cur[d], 1);
        col[pos] = src[e];
    }
}

// ---------------- input projection: relu(ln(x @ W_in + b_in)) ----------------
__global__ void k_input_proj(const float* __restrict__ x, const float* __restrict__ W,
                             const float* __restrict__ b, const float* __restrict__ g,
                             const float* __restrict__ be, float* __restrict__ out) {
    int n = blockIdx.x, f = threadIdx.x;
    __shared__ float xs[16];
    __shared__ float red[8];
    if (f < 15) xs[f] = x[n * 15 + f];
    __syncthreads();
    float acc = b[f];
    #pragma unroll
    for (int k = 0; k < 15; k++) acc = fmaf(xs[k], W[k * 128 + f], acc);
    float y = block_ln_128(acc, g[f], be[f], red);
    out[n * 128 + f] = fmaxf(y, 0.0f);
}

// ---------------- SGEMM: C[M,128] = A[M,128] @ op(B[128,128]) (+bias) ----------------
// BM=128, BN=128, BK=16, 256 threads, 8x8 microtile, f32x2 packed FFMA.
// TRANSB=0: C[n,f] = sum_k A[n,k]*B[k,f]   TRANSB=1: C[n,f] = sum_k A[n,k]*B[f,k]
template <int TRANSB, int BIAS>
__device__ __forceinline__ void gemm_dev(const float* __restrict__ A,
                                         const float* __restrict__ B,
                                         const float* __restrict__ bias,
                                         float* __restrict__ C) {
    __shared__ float As[16][132];
    __shared__ float Bs[16][132];
    const int t = threadIdx.x;
    const int tx = t & 15, ty = t >> 4;
    const int row0 = blockIdx.x * 128;
    const int rA = t >> 2;               // 0..63 (u adds 64)
    const int cgA = (t & 3) * 4;         // 0,4,8,12

    ull acc[4][8];
    #pragma unroll
    for (int p = 0; p < 4; p++)
        #pragma unroll
        for (int j = 0; j < 8; j++) acc[p][j] = 0ull;

    float4 ra[2], rb[2];
    // prologue: fetch tile 0
    #pragma unroll
    for (int u = 0; u < 2; u++)
        ra[u] = *(const float4*)&A[(row0 + rA + u * 64) * 128 + cgA];
    if (TRANSB) {
        #pragma unroll
        for (int u = 0; u < 2; u++)
            rb[u] = *(const float4*)&B[(rA + u * 64) * 128 + cgA];
    } else {
        #pragma unroll
        for (int u = 0; u < 2; u++) {
            int idx = t + u * 256; int kk = idx >> 5, cc = (idx & 31) * 4;
            rb[u] = *(const float4*)&B[kk * 128 + cc];
        }
    }

    for (int kt = 0; kt < 8; kt++) {
        // store staged regs
        #pragma unroll
        for (int u = 0; u < 2; u++) {
            int r = rA + u * 64;
            As[cgA + 0][r] = ra[u].x; As[cgA + 1][r] = ra[u].y;
            As[cgA + 2][r] = ra[u].z; As[cgA + 3][r] = ra[u].w;
        }
        if (TRANSB) {
            #pragma unroll
            for (int u = 0; u < 2; u++) {
                int f = rA + u * 64;
                Bs[cgA + 0][f] = rb[u].x; Bs[cgA + 1][f] = rb[u].y;
                Bs[cgA + 2][f] = rb[u].z; Bs[cgA + 3][f] = rb[u].w;
            }
        } else {
            #pragma unroll
            for (int u = 0; u < 2; u++) {
                int idx = t + u * 256; int kk = idx >> 5, cc = (idx & 31) * 4;
                *(float4*)&Bs[kk][cc] = rb[u];
            }
        }
        __syncthreads();
        // prefetch next tile into regs
        if (kt < 7) {
            int k0 = (kt + 1) * 16;
            #pragma unroll
            for (int u = 0; u < 2; u++)
                ra[u] = *(const float4*)&A[(row0 + rA + u * 64) * 128 + k0 + cgA];
            if (TRANSB) {
                #pragma unroll
                for (int u = 0; u < 2; u++)
                    rb[u] = *(const float4*)&B[(rA + u * 64) * 128 + k0 + cgA];
            } else {
                #pragma unroll
                for (int u = 0; u < 2; u++) {
                    int idx = t + u * 256; int kk = idx >> 5, cc = (idx & 31) * 4;
                    rb[u] = *(const float4*)&B[(k0 + kk) * 128 + cc];
                }
            }
        }
        // compute 16 k-steps
        #pragma unroll
        for (int k = 0; k < 16; k++) {
            float4 a0 = *(const float4*)&As[k][ty * 4];
            float4 a1 = *(const float4*)&As[k][ty * 4 + 64];
            float4 b0 = *(const float4*)&Bs[k][tx * 4];
            float4 b1 = *(const float4*)&Bs[k][tx * 4 + 64];
            ull ap[4] = { pk2(a0.x, a0.y), pk2(a0.z, a0.w),
                          pk2(a1.x, a1.y), pk2(a1.z, a1.w) };
            float bf[8] = { b0.x, b0.y, b0.z, b0.w, b1.x, b1.y, b1.z, b1.w };
            #pragma unroll
            for (int j = 0; j < 8; j++) {
                ull bs = pk2(bf[j], bf[j]);
                #pragma unroll
                for (int p = 0; p < 4; p++) acc[p][j] = fma2(ap[p], bs, acc[p][j]);
            }
        }
        __syncthreads();
    }

    float4 bb0, bb1;
    if (BIAS) {
        bb0 = *(const float4*)&bias[tx * 4];
        bb1 = *(const float4*)&bias[tx * 4 + 64];
    } else {
        bb0 = make_float4(0.f, 0.f, 0.f, 0.f); bb1 = bb0;
    }
    #pragma unroll
    for (int p = 0; p < 4; p++) {
        int rlo = row0 + ty * 4 + (p >> 1) * 64 + (p & 1) * 2;   // pair rows rlo, rlo+1
        float lo[8], hi[8];
        #pragma unroll
        for (int j = 0; j < 8; j++) up2(acc[p][j], lo[j], hi[j]);
        *(float4*)&C[rlo * 128 + tx * 4] =
            make_float4(lo[0] + bb0.x, lo[1] + bb0.y, lo[2] + bb0.z, lo[3] + bb0.w);
        *(float4*)&C[rlo * 128 + tx * 4 + 64] =
            make_float4(lo[4] + bb1.x, lo[5] + bb1.y, lo[6] + bb1.z, lo[7] + bb1.w);
        *(float4*)&C[(rlo + 1) * 128 + tx * 4] =
            make_float4(hi[0] + bb0.x, hi[1] + bb0.y, hi[2] + bb0.z, hi[3] + bb0.w);
        *(float4*)&C[(rlo + 1) * 128 + tx * 4 + 64] =
            make_float4(hi[4] + bb1.x, hi[5] + bb1.y, hi[6] + bb1.z, hi[7] + bb1.w);
    }
}

template <int TRANSB, int BIAS>
__global__ __launch_bounds__(256, 2) void k_gemm2(const float* __restrict__ A,
                                                  const float* __restrict__ B,
                                                  const float* __restrict__ bias,
                                                  float* __restrict__ C) {
    gemm_dev<TRANSB, BIAS>(A, B, bias, C);
}

// fused QKV: grid.y in {0,1,2} selects weight/bias/output
__global__ __launch_bounds__(256, 2) void k_gemm_qkv(const float* __restrict__ A,
    const float* __restrict__ Wq, const float* __restrict__ bq, float* __restrict__ q,
    const float* __restrict__ Wk, const float* __restrict__ bk, float* __restrict__ k,
    const float* __restrict__ Wv, const float* __restrict__ bv, float* __restrict__ v) {
    int s = blockIdx.y;
    const float* B  = (s == 0) ? Wq : (s == 1) ? Wk : Wv;
    const float* bi = (s == 0) ? bq : (s == 1) ? bk : bv;
    float*       C  = (s == 0) ? q  : (s == 1) ? k  : v;
    gemm_dev<1, 1>(A, B, bi, C);
}

// ---------------- GCN aggregate + bias + LN + relu + residual (warp per node) ----------------
__global__ __launch_bounds__(128) void k_gcn_agg(const float* __restrict__ hw,
                          const float* __restrict__ hin,
                          const int* __restrict__ rp, const int* __restrict__ col,
                          const float* __restrict__ dis,
                          const float* __restrict__ bc, const float* __restrict__ gn,
                          const float* __restrict__ bn, float* __restrict__ hout,
                          int residual) {
    const int lane = threadIdx.x & 31;
    const int n = blockIdx.x * 4 + (threadIdx.x >> 5);
    const float dn = dis[n];

    float4 sv = *(const float4*)(hw + (size_t)n * 128 + lane * 4);
    ull a0 = pk2(dn * sv.x, dn * sv.y);
    ull a1 = pk2(dn * sv.z, dn * sv.w);

    int e = rp[n], end = rp[n + 1];
    for (; e + 4 <= end; e += 4) {
        int s0 = __ldg(&col[e]),     s1 = __ldg(&col[e + 1]);
        int s2 = __ldg(&col[e + 2]), s3 = __ldg(&col[e + 3]);
        float w0 = __ldg(&dis[s0]), w1 = __ldg(&dis[s1]);
        float w2 = __ldg(&dis[s2]), w3 = __ldg(&dis[s3]);
        float4 v0 = *(const float4*)(hw + (size_t)s0 * 128 + lane * 4);
        float4 v1 = *(const float4*)(hw + (size_t)s1 * 128 + lane * 4);
        float4 v2 = *(const float4*)(hw + (size_t)s2 * 128 + lane * 4);
        float4 v3 = *(const float4*)(hw + (size_t)s3 * 128 + lane * 4);
        ull wp0 = pk2(w0, w0), wp1 = pk2(w1, w1), wp2 = pk2(w2, w2), wp3 = pk2(w3, w3);
        a0 = fma2(wp0, pk2(v0.x, v0.y), a0); a1 = fma2(wp0, pk2(v0.z, v0.w), a1);
        a0 = fma2(wp1, pk2(v1.x, v1.y), a0); a1 = fma2(wp1, pk2(v1.z, v1.w), a1);
        a0 = fma2(wp2, pk2(v2.x, v2.y), a0); a1 = fma2(wp2, pk2(v2.z, v2.w), a1);
        a0 = fma2(wp3, pk2(v3.x, v3.y), a0); a1 = fma2(wp3, pk2(v3.z, v3.w), a1);
    }
    for (; e < end; e++) {
        int s = __ldg(&col[e]);
        float w = __ldg(&dis[s]);
        float4 v0 = *(const float4*)(hw + (size_t)s * 128 + lane * 4);
        ull wp = pk2(w, w);
        a0 = fma2(wp, pk2(v0.x, v0.y), a0);
        a1 = fma2(wp, pk2(v0.z, v0.w), a1);
    }

    float x0, x1, x2, x3;
    up2(a0, x0, x1); up2(a1, x2, x3);
    float4 bcv = *(const float4*)&bc[lane * 4];
    x0 = fmaf(dn, x0, bcv.x); x1 = fmaf(dn, x1, bcv.y);
    x2 = fmaf(dn, x2, bcv.z); x3 = fmaf(dn, x3, bcv.w);

    // LayerNorm over 128 (4 per lane x 32 lanes) — warp butterfly
    float s  = x0 + x1 + x2 + x3;
    float s2 = x0 * x0 + x1 * x1 + x2 * x2 + x3 * x3;
    #pragma unroll
    for (int o = 16; o > 0; o >>= 1) {
        s  += __shfl_xor_sync(0xffffffffu, s,  o);
        s2 += __shfl_xor_sync(0xffffffffu, s2, o);
    }
    float m   = s  * (1.0f / 128.0f);
    float var = s2 * (1.0f / 128.0f) - m * m;
    float r   = rsqrtf(var + 1e-5f);

    float4 gv = *(const float4*)&gn[lane * 4];
    float4 bv = *(const float4*)&bn[lane * 4];
    float y0 = fmaxf((x0 - m) * r * gv.x + bv.x, 0.0f);
    float y1 = fmaxf((x1 - m) * r * gv.y + bv.y, 0.0f);
    float y2 = fmaxf((x2 - m) * r * gv.z + bv.z, 0.0f);
    float y3 = fmaxf((x3 - m) * r * gv.w + bv.w, 0.0f);
    if (residual) {
        float4 hr = *(const float4*)(hin + (size_t)n * 128 + lane * 4);
        y0 += hr.x; y1 += hr.y; y2 += hr.z; y3 += hr.w;
    }
    *(float4*)(hout + (size_t)n * 128 + lane * 4) = make_float4(y0, y1, y2, y3);
}

// ---------------- attention: one block per (graph, head), no-max online softmax ----------------
__global__ __launch_bounds__(256) void k_attn(const float* __restrict__ qg,
                                              const float* __restrict__ kg,
                                              const float* __restrict__ vg,
                                              float* __restrict__ og) {
    __shared__ float4 Ks[256][4];
    __shared__ float4 Vs[256][4];
    int g = blockIdx.x >> 3;
    int h = blockIdx.x & 7;
    int t = threadIdx.x;
    const size_t base = (size_t)(g * NPG) * 128 + h * 16;

    {
        const float4* kp = (const float4*)(kg + base + (size_t)t * 128);
        const float4* vp = (const float4*)(vg + base + (size_t)t * 128);
        Ks[t][0] = kp[0]; Ks[t][1] = kp[1]; Ks[t][2] = kp[2]; Ks[t][3] = kp[3];
        Vs[t][0] = vp[0]; Vs[t][1] = vp[1]; Vs[t][2] = vp[2]; Vs[t][3] = vp[3];
    }
    float qr[16];
    {
        const float4* qp = (const float4*)(qg + base + (size_t)t * 128);
        float4 a = qp[0], b = qp[1], c = qp[2], d = qp[3];
        qr[0]=a.x*0.25f;  qr[1]=a.y*0.25f;  qr[2]=a.z*0.25f;  qr[3]=a.w*0.25f;
        qr[4]=b.x*0.25f;  qr[5]=b.y*0.25f;  qr[6]=b.z*0.25f;  qr[7]=b.w*0.25f;
        qr[8]=c.x*0.25f;  qr[9]=c.y*0.25f;  qr[10]=c.z*0.25f; qr[11]=c.w*0.25f;
        qr[12]=d.x*0.25f; qr[13]=d.y*0.25f; qr[14]=d.z*0.25f; qr[15]=d.w*0.25f;
    }
    __syncthreads();

    float l = 0.0f;
    ull acc[8];
    #pragma unroll
    for (int i = 0; i < 8; i++) acc[i] = 0ull;

    #pragma unroll 4
    for (int j = 0; j < 256; j++) {
        float4 k0 = Ks[j][0], k1 = Ks[j][1], k2 = Ks[j][2], k3 = Ks[j][3];
        float sA = qr[0]*k0.x + qr[1]*k0.y + qr[2]*k0.z + qr[3]*k0.w;
        float sB = qr[4]*k1.x + qr[5]*k1.y + qr[6]*k1.z + qr[7]*k1.w;
        float sC = qr[8]*k2.x + qr[9]*k2.y + qr[10]*k2.z + qr[11]*k2.w;
        float sD = qr[12]*k3.x + qr[13]*k3.y + qr[14]*k3.z + qr[15]*k3.w;
        float s = (sA + sB) + (sC + sD);
        float p = __expf(fminf(s, 60.0f));
        l += p;
        ull pp = pk2(p, p);
        float4 v0 = Vs[j][0], v1 = Vs[j][1], v2 = Vs[j][2], v3 = Vs[j][3];
        acc[0] = fma2(pp, pk2(v0.x, v0.y), acc[0]);
        acc[1] = fma2(pp, pk2(v0.z, v0.w), acc[1]);
        acc[2] = fma2(pp, pk2(v1.x, v1.y), acc[2]);
        acc[3] = fma2(pp, pk2(v1.z, v1.w), acc[3]);
        acc[4] = fma2(pp, pk2(v2.x, v2.y), acc[4]);
        acc[5] = fma2(pp, pk2(v2.z, v2.w), acc[5]);
        acc[6] = fma2(pp, pk2(v3.x, v3.y), acc[6]);
        acc[7] = fma2(pp, pk2(v3.z, v3.w), acc[7]);
    }
    float inv = 1.0f / l;
    float o[16];
    #pragma unroll
    for (int i = 0; i < 8; i++) {
        up2(acc[i], o[2*i], o[2*i+1]);
        o[2*i] *= inv; o[2*i+1] *= inv;
    }
    float4* op = (float4*)(og + base + (size_t)t * 128);
    op[0] = make_float4(o[0],  o[1],  o[2],  o[3]);
    op[1] = make_float4(o[4],  o[5],  o[6],  o[7]);
    op[2] = make_float4(o[8],  o[9],  o[10], o[11]);
    op[3] = make_float4(o[12], o[13], o[14], o[15]);
}

// ---------------- out-proj residual LN ----------------
__global__ void k_ln_res(const float* __restrict__ o2, const float* __restrict__ hres,
                         const float* __restrict__ ga, const float* __restrict__ ba,
                         float* __restrict__ out) {
    int n = blockIdx.x, f = threadIdx.x;
    __shared__ float red[8];
    float v = o2[n * 128 + f] + hres[n * 128 + f];
    out[n * 128 + f] = block_ln_128(v, ga[f], ba[f], red);
}

// ---------------- pooling: [mean, max, sum] per graph ----------------
__global__ void k_pool(const float* __restrict__ h, float* __restrict__ pooled) {
    int g = blockIdx.x, f = threadIdx.x;
    float s = 0.0f, mx = -1e30f;
    const float* p = h + (size_t)(g * NPG) * 128 + f;
    #pragma unroll 8
    for (int j = 0; j < NPG; j++) {
        float v = p[j * 128];
        s += v;
        mx = fmaxf(mx, v);
    }
    pooled[g * 384 + f]       = s * (1.0f / 256.0f);
    pooled[g * 384 + 128 + f] = mx;
    pooled[g * 384 + 256 + f] = s;
}

// ---------------- classifier ----------------
__global__ void k_classifier(const float* __restrict__ pooled,
                             const float* __restrict__ W1, const float* __restrict__ b1,
                             const float* __restrict__ g1, const float* __restrict__ beta1,
                             const float* __restrict__ W2, const float* __restrict__ b2,
                             const float* __restrict__ W3, const float* __restrict__ b3,
                             float* __restrict__ out) {
    int g = blockIdx.x, f = threadIdx.x;
    __shared__ float ps[384];
    __shared__ float z1[128];
    __shared__ float z2[64];
    __shared__ float red[8];
    for (int i = f; i < 384; i += 128) ps[i] = pooled[g * 384 + i];
    __syncthreads();
    float acc = b1[f];
    for (int k = 0; k < 384; k++) acc = fmaf(ps[k], W1[k * 128 + f], acc);
    float y = fmaxf(block_ln_128(acc, g1[f], beta1[f], red), 0.0f);
    z1[f] = y;
    __syncthreads();
    if (f < 64) {
        float a = b2[f];
        #pragma unroll 8
        for (int k = 0; k < 128; k++) a = fmaf(z1[k], W2[k * 64 + f], a);
        z2[f] = fmaxf(a, 0.0f);
    }
    __syncthreads();
    if (f < 2) {
        float a = b3[f];
        #pragma unroll
        for (int k = 0; k < 64; k++) a = fmaf(z2[k], W3[k * 2 + f], a);
        out[g * 2 + f] = a;
    }
}

// ---------------- launch ----------------
extern "C" void kernel_launch(void* const* d_in, const int* in_sizes, int n_in,
                              void* d_out, int out_size) {
    const float* x     = (const float*)d_in[0];
    const int*   ei    = (const int*)  d_in[1];
    // d_in[2] = batch (unused; graphs are equal-sized)
    const float* W_in  = (const float*)d_in[3];
    const float* b_in  = (const float*)d_in[4];
    const float* g_in  = (const float*)d_in[5];
    const float* be_in = (const float*)d_in[6];
    const float* Wc    = (const float*)d_in[7];
    const float* bc    = (const float*)d_in[8];
    const float* gn    = (const float*)d_in[9];
    const float* bn    = (const float*)d_in[10];
    const float* Wq    = (const float*)d_in[11];
    const float* bq    = (const float*)d_in[12];
    const float* Wk    = (const float*)d_in[13];
    const float* bk    = (const float*)d_in[14];
    const float* Wv    = (const float*)d_in[15];
    const float* bv    = (const float*)d_in[16];
    const float* Wo    = (const float*)d_in[17];
    const float* bo    = (const float*)d_in[18];
    const float* ga    = (const float*)d_in[19];
    const float* ba    = (const float*)d_in[20];
    const float* W1    = (const float*)d_in[21];
    const float* b1    = (const float*)d_in[22];
    const float* g1    = (const float*)d_in[23];
    const float* beta1 = (const float*)d_in[24];
    const float* W2    = (const float*)d_in[25];
    const float* b2    = (const float*)d_in[26];
    const float* W3    = (const float*)d_in[27];
    const float* b3    = (const float*)d_in[28];
    float* out = (float*)d_out;

    const int* src = ei;
    const int* dst = ei + EE;

    float *p_h, *p_h2, *p_tmp, *p_q, *p_k, *p_v, *p_pool, *p_dis;
    int *p_deg, *p_rp, *p_cur, *p_col;
    cudaGetSymbolAddress((void**)&p_h,   g_h);
    cudaGetSymbolAddress((void**)&p_h2,  g_h2);
    cudaGetSymbolAddress((void**)&p_tmp, g_tmp);
    cudaGetSymbolAddress((void**)&p_q,   g_q);
    cudaGetSymbolAddress((void**)&p_k,   g_k);
    cudaGetSymbolAddress((void**)&p_v,   g_v);
    cudaGetSymbolAddress((void**)&p_pool,g_pooled);
    cudaGetSymbolAddress((void**)&p_deg, g_deg);
    cudaGetSymbolAddress((void**)&p_rp,  g_rp);
    cudaGetSymbolAddress((void**)&p_cur, g_cur);
    cudaGetSymbolAddress((void**)&p_col, g_col);
    cudaGetSymbolAddress((void**)&p_dis, g_dis);

    // --- CSR build ---
    cudaMemsetAsync(p_deg, 0, NN * sizeof(int));
    k_hist<<<EE / 256, 256>>>(dst, p_deg);
    k_scan<<<1, 1024>>>(p_deg, p_rp, p_cur, p_dis);
    k_fill<<<EE / 256, 256>>>(src, dst, p_cur, p_col);

    // --- input projection ---
    k_input_proj<<<NN, 128>>>(x, W_in, b_in, g_in, be_in, p_h);

    // --- 3 GCN layers (ping-pong h buffers) ---
    float* cur = p_h;
    float* nxt = p_h2;
    for (int i = 0; i < NLAYERS; i++) {
        k_gemm2<0, 0><<<NN / 128, 256>>>(cur, Wc + i * HID * HID, nullptr, p_tmp);
        k_gcn_agg<<<NN / 4, 128>>>(p_tmp, cur, p_rp, p_col, p_dis,
                                   bc + i * HID, gn + i * HID, bn + i * HID, nxt, i > 0);
        float* t = cur; cur = nxt; nxt = t;
    }
    // after 3 layers: cur == p_h2

    // --- MHA ---
    {
        dim3 grid(NN / 128, 3);
        k_gemm_qkv<<<grid, 256>>>(cur, Wq, bq, p_q, Wk, bk, p_k, Wv, bv, p_v);
    }
    k_attn<<<GG * NH, 256>>>(p_q, p_k, p_v, p_tmp);
    k_gemm2<1, 1><<<NN / 128, 256>>>(p_tmp, Wo, bo, p_q);    // p_q free, reuse
    k_ln_res<<<NN, 128>>>(p_q, cur, ga, ba, nxt);            // nxt == p_h, free

    // --- pooling + classifier ---
    k_pool<<<GG, 128>>>(nxt, p_pool);
    k_classifier<<<GG, 128>>>(p_pool, W1, b1, g1, beta1, W2, b2, W3, b3, out);
}

// round 3
// speedup vs baseline: 1.3965x; 1.0941x over previous
#include <cuda_runtime.h>
#include <math.h>

#define NN      32768      // nodes
#define GG      128        // graphs
#define NPG     256        // nodes per graph
#define HID     128
#define NH      8
#define DH      16
#define EE      1048576    // edges
#define NLAYERS 3

typedef unsigned long long ull;
typedef unsigned int uint;
typedef unsigned short ushort;

// ---------------- packed f32x2 helpers ----------------
__device__ __forceinline__ ull pk2(float lo, float hi) {
    ull r; asm("mov.b64 %0,{%1,%2};" : "=l"(r) : "f"(lo), "f"(hi)); return r;
}
__device__ __forceinline__ void up2(ull v, float& lo, float& hi) {
    asm("mov.b64 {%0,%1},%2;" : "=f"(lo), "=f"(hi) : "l"(v));
}
__device__ __forceinline__ ull fma2(ull a, ull b, ull c) {
    ull d; asm("fma.rn.f32x2 %0,%1,%2,%3;" : "=l"(d) : "l"(a), "l"(b), "l"(c)); return d;
}
__device__ __forceinline__ ull add2(ull a, ull b) {
    ull d; asm("add.rn.f32x2 %0,%1,%2;" : "=l"(d) : "l"(a), "l"(b)); return d;
}
// pack 2 fp32 -> bf16x2 (lo in low half)
__device__ __forceinline__ uint bf2(float lo, float hi) {
    uint r; asm("cvt.rn.bf16x2.f32 %0,%1,%2;" : "=r"(r) : "f"(hi), "f"(lo)); return r;
}
// unpack bf16x2 word -> 2 fp32
__device__ __forceinline__ float4 bf4(uint2 u) {
    float4 r;
    r.x = __uint_as_float(u.x << 16);
    r.y = __uint_as_float(u.x & 0xffff0000u);
    r.z = __uint_as_float(u.y << 16);
    r.w = __uint_as_float(u.y & 0xffff0000u);
    return r;
}

// ---------------- scratch (device globals; no runtime alloc allowed) ----------------
__device__ float  g_h   [NN * HID];
__device__ float  g_h2  [NN * HID];
__device__ float  g_tmp [NN * HID];
__device__ float  g_q   [NN * HID];
__device__ float  g_k   [NN * HID];
__device__ float  g_v   [NN * HID];
__device__ ushort g_hwbf[NN * HID];     // bf16 GCN-GEMM output for aggregation
__device__ float  g_pooled[GG * 3 * HID];
__device__ int    g_deg[NN];
__device__ int    g_rp [NN + 1];
__device__ int    g_cur[NN];
__device__ int    g_col[EE];
__device__ float  g_dis[NN];

// ---------------- block LN (128 threads) ----------------
__device__ __forceinline__ float block_ln_128(float v, float gamma, float beta, float* sh) {
    float s = v, s2 = v * v;
    #pragma unroll
    for (int o = 16; o > 0; o >>= 1) {
        s  += __shfl_down_sync(0xffffffffu, s,  o);
        s2 += __shfl_down_sync(0xffffffffu, s2, o);
    }
    int w = threadIdx.x >> 5, l = threadIdx.x & 31;
    if (l == 0) { sh[w] = s; sh[4 + w] = s2; }
    __syncthreads();
    float ts  = sh[0] + sh[1] + sh[2] + sh[3];
    float ts2 = sh[4] + sh[5] + sh[6] + sh[7];
    float m   = ts  * (1.0f / 128.0f);
    float var = ts2 * (1.0f / 128.0f) - m * m;
    float r   = rsqrtf(var + 1e-5f);
    __syncthreads();
    return (v - m) * r * gamma + beta;
}

// ---------------- CSR build ----------------
__global__ void k_hist(const int* __restrict__ dst, int* __restrict__ deg) {
    int e = blockIdx.x * blockDim.x + threadIdx.x;
    if (e < EE) atomicAdd(&deg[dst[e]], 1);
}

__global__ void k_scan(const int* __restrict__ deg, int* __restrict__ rp,
                       int* __restrict__ cur, float* __restrict__ dis) {
    __shared__ int part[1024];
    int tid = threadIdx.x;            // 1024 threads
    int base = tid * 32;
    int v[32];
    int s = 0;
    #pragma unroll
    for (int i = 0; i < 32; i++) { v[i] = deg[base + i]; s += v[i]; }
    part[tid] = s;
    __syncthreads();
    for (int off = 1; off < 1024; off <<= 1) {
        int t = (tid >= off) ? part[tid - off] : 0;
        __syncthreads();
        part[tid] += t;
        __syncthreads();
    }
    int run = part[tid] - s;          // exclusive prefix
    #pragma unroll
    for (int i = 0; i < 32; i++) {
        rp[base + i]  = run;
        cur[base + i] = run;
        dis[base + i] = rsqrtf((float)v[i] + 1.0f);  // +1 self loop
        run += v[i];
    }
    if (tid == 1023) rp[NN] = run;
}

__global__ void k_fill(const int* __restrict__ src, const int* __restrict__ dst,
                       int* __restrict__ cur, int* __restrict__ col) {
    int e = blockIdx.x * blockDim.x + threadIdx.x;
    if (e < EE) {
        int d = dst[e];
        int pos = atomicAdd(&cur[d], 1);
        col[pos] = src[e];
    }
}

// ---------------- input projection: relu(ln(x @ W_in + b_in)), warp per node ----------------
__global__ __launch_bounds__(256) void k_input_proj(const float* __restrict__ x,
                             const float* __restrict__ W,
                             const float* __restrict__ b, const float* __restrict__ g,
                             const float* __restrict__ be, float* __restrict__ out) {
    const int lane = threadIdx.x & 31;
    const int n = blockIdx.x * 8 + (threadIdx.x >> 5);
    float xv = (lane < 15) ? __ldg(&x[n * 15 + lane]) : 0.0f;
    float4 acc = *(const float4*)&b[lane * 4];
    #pragma unroll
    for (int k = 0; k < 15; k++) {
        float xk = __shfl_sync(0xffffffffu, xv, k);
        float4 w = *(const float4*)&W[k * 128 + lane * 4];
        acc.x = fmaf(xk, w.x, acc.x); acc.y = fmaf(xk, w.y, acc.y);
        acc.z = fmaf(xk, w.z, acc.z); acc.w = fmaf(xk, w.w, acc.w);
    }
    // warp LN over 128
    float s  = acc.x + acc.y + acc.z + acc.w;
    float s2 = acc.x*acc.x + acc.y*acc.y + acc.z*acc.z + acc.w*acc.w;
    #pragma unroll
    for (int o = 16; o > 0; o >>= 1) {
        s  += __shfl_xor_sync(0xffffffffu, s,  o);
        s2 += __shfl_xor_sync(0xffffffffu, s2, o);
    }
    float m   = s * (1.0f / 128.0f);
    float var = s2 * (1.0f / 128.0f) - m * m;
    float r   = rsqrtf(var + 1e-5f);
    float4 gv = *(const float4*)&g[lane * 4];
    float4 bv = *(const float4*)&be[lane * 4];
    float4 y;
    y.x = fmaxf((acc.x - m) * r * gv.x + bv.x, 0.0f);
    y.y = fmaxf((acc.y - m) * r * gv.y + bv.y, 0.0f);
    y.z = fmaxf((acc.z - m) * r * gv.z + bv.z, 0.0f);
    y.w = fmaxf((acc.w - m) * r * gv.w + bv.w, 0.0f);
    *(float4*)(out + (size_t)n * 128 + lane * 4) = y;
}

// ---------------- SGEMM: C[M,128] = A[M,128] @ op(B[128,128]) (+bias) ----------------
// BM=128, BN=128, BK=16, 256 threads, 8x8 microtile, f32x2 packed FFMA.
// BF16OUT=1: write bf16 (for GCN aggregation input); else fp32.
template <int TRANSB, int BIAS, int BF16OUT>
__device__ __forceinline__ void gemm_dev(const float* __restrict__ A,
                                         const float* __restrict__ B,
                                         const float* __restrict__ bias,
                                         void* __restrict__ Cv) {
    __shared__ float As[16][132];
    __shared__ float Bs[16][132];
    const int t = threadIdx.x;
    const int tx = t & 15, ty = t >> 4;
    const int row0 = blockIdx.x * 128;
    const int rA = t >> 2;               // 0..63 (u adds 64)
    const int cgA = (t & 3) * 4;         // 0,4,8,12

    ull acc[4][8];
    #pragma unroll
    for (int p = 0; p < 4; p++)
        #pragma unroll
        for (int j = 0; j < 8; j++) acc[p][j] = 0ull;

    float4 ra[2], rb[2];
    #pragma unroll
    for (int u = 0; u < 2; u++)
        ra[u] = *(const float4*)&A[(row0 + rA + u * 64) * 128 + cgA];
    if (TRANSB) {
        #pragma unroll
        for (int u = 0; u < 2; u++)
            rb[u] = *(const float4*)&B[(rA + u * 64) * 128 + cgA];
    } else {
        #pragma unroll
        for (int u = 0; u < 2; u++) {
            int idx = t + u * 256; int kk = idx >> 5, cc = (idx & 31) * 4;
            rb[u] = *(const float4*)&B[kk * 128 + cc];
        }
    }

    for (int kt = 0; kt < 8; kt++) {
        #pragma unroll
        for (int u = 0; u < 2; u++) {
            int r = rA + u * 64;
            As[cgA + 0][r] = ra[u].x; As[cgA + 1][r] = ra[u].y;
            As[cgA + 2][r] = ra[u].z; As[cgA + 3][r] = ra[u].w;
        }
        if (TRANSB) {
            #pragma unroll
            for (int u = 0; u < 2; u++) {
                int f = rA + u * 64;
                Bs[cgA + 0][f] = rb[u].x; Bs[cgA + 1][f] = rb[u].y;
                Bs[cgA + 2][f] = rb[u].z; Bs[cgA + 3][f] = rb[u].w;
            }
        } else {
            #pragma unroll
            for (int u = 0; u < 2; u++) {
                int idx = t + u * 256; int kk = idx >> 5, cc = (idx & 31) * 4;
                *(float4*)&Bs[kk][cc] = rb[u];
            }
        }
        __syncthreads();
        if (kt < 7) {
            int k0 = (kt + 1) * 16;
            #pragma unroll
            for (int u = 0; u < 2; u++)
                ra[u] = *(const float4*)&A[(row0 + rA + u * 64) * 128 + k0 + cgA];
            if (TRANSB) {
                #pragma unroll
                for (int u = 0; u < 2; u++)
                    rb[u] = *(const float4*)&B[(rA + u * 64) * 128 + k0 + cgA];
            } else {
                #pragma unroll
                for (int u = 0; u < 2; u++) {
                    int idx = t + u * 256; int kk = idx >> 5, cc = (idx & 31) * 4;
                    rb[u] = *(const float4*)&B[(k0 + kk) * 128 + cc];
                }
            }
        }
        #pragma unroll
        for (int k = 0; k < 16; k++) {
            float4 a0 = *(const float4*)&As[k][ty * 4];
            float4 a1 = *(const float4*)&As[k][ty * 4 + 64];
            float4 b0 = *(const float4*)&Bs[k][tx * 4];
            float4 b1 = *(const float4*)&Bs[k][tx * 4 + 64];
            ull ap[4] = { pk2(a0.x, a0.y), pk2(a0.z, a0.w),
                          pk2(a1.x, a1.y), pk2(a1.z, a1.w) };
            float bf[8] = { b0.x, b0.y, b0.z, b0.w, b1.x, b1.y, b1.z, b1.w };
            #pragma unroll
            for (int j = 0; j < 8; j++) {
                ull bs = pk2(bf[j], bf[j]);
                #pragma unroll
                for (int p = 0; p < 4; p++) acc[p][j] = fma2(ap[p], bs, acc[p][j]);
            }
        }
        __syncthreads();
    }

    float4 bb0, bb1;
    if (BIAS) {
        bb0 = *(const float4*)&bias[tx * 4];
        bb1 = *(const float4*)&bias[tx * 4 + 64];
    } else {
        bb0 = make_float4(0.f, 0.f, 0.f, 0.f); bb1 = bb0;
    }
    #pragma unroll
    for (int p = 0; p < 4; p++) {
        int rlo = row0 + ty * 4 + (p >> 1) * 64 + (p & 1) * 2;   // rows rlo, rlo+1
        float lo[8], hi[8];
        #pragma unroll
        for (int j = 0; j < 8; j++) up2(acc[p][j], lo[j], hi[j]);
        lo[0] += bb0.x; lo[1] += bb0.y; lo[2] += bb0.z; lo[3] += bb0.w;
        lo[4] += bb1.x; lo[5] += bb1.y; lo[6] += bb1.z; lo[7] += bb1.w;
        hi[0] += bb0.x; hi[1] += bb0.y; hi[2] += bb0.z; hi[3] += bb0.w;
        hi[4] += bb1.x; hi[5] += bb1.y; hi[6] += bb1.z; hi[7] += bb1.w;
        if (BF16OUT) {
            ushort* Cb = (ushort*)Cv;
            *(uint2*)(Cb + (size_t)rlo * 128 + tx * 4) =
                make_uint2(bf2(lo[0], lo[1]), bf2(lo[2], lo[3]));
            *(uint2*)(Cb + (size_t)rlo * 128 + tx * 4 + 64) =
                make_uint2(bf2(lo[4], lo[5]), bf2(lo[6], lo[7]));
            *(uint2*)(Cb + (size_t)(rlo + 1) * 128 + tx * 4) =
                make_uint2(bf2(hi[0], hi[1]), bf2(hi[2], hi[3]));
            *(uint2*)(Cb + (size_t)(rlo + 1) * 128 + tx * 4 + 64) =
                make_uint2(bf2(hi[4], hi[5]), bf2(hi[6], hi[7]));
        } else {
            float* C = (float*)Cv;
            *(float4*)&C[(size_t)rlo * 128 + tx * 4]      = make_float4(lo[0], lo[1], lo[2], lo[3]);
            *(float4*)&C[(size_t)rlo * 128 + tx * 4 + 64] = make_float4(lo[4], lo[5], lo[6], lo[7]);
            *(float4*)&C[(size_t)(rlo+1) * 128 + tx * 4]      = make_float4(hi[0], hi[1], hi[2], hi[3]);
            *(float4*)&C[(size_t)(rlo+1) * 128 + tx * 4 + 64] = make_float4(hi[4], hi[5], hi[6], hi[7]);
        }
    }
}

template <int TRANSB, int BIAS, int BF16OUT>
__global__ __launch_bounds__(256, 2) void k_gemm2(const float* __restrict__ A,
                                                  const float* __restrict__ B,
                                                  const float* __restrict__ bias,
                                                  void* __restrict__ C) {
    gemm_dev<TRANSB, BIAS, BF16OUT>(A, B, bias, C);
}

// fused QKV: grid.y in {0,1,2} selects weight/bias/output
__global__ __launch_bounds__(256, 2) void k_gemm_qkv(const float* __restrict__ A,
    const float* __restrict__ Wq, const float* __restrict__ bq, float* __restrict__ q,
    const float* __restrict__ Wk, const float* __restrict__ bk, float* __restrict__ k,
    const float* __restrict__ Wv, const float* __restrict__ bv, float* __restrict__ v) {
    int s = blockIdx.y;
    const float* B  = (s == 0) ? Wq : (s == 1) ? Wk : Wv;
    const float* bi = (s == 0) ? bq : (s == 1) ? bk : bv;
    float*       C  = (s == 0) ? q  : (s == 1) ? k  : v;
    gemm_dev<1, 1, 0>(A, B, bi, C);
}

// ---------------- GCN aggregate (bf16 rows) + bias + LN + relu + residual ----------------
__global__ __launch_bounds__(128) void k_gcn_agg(const ushort* __restrict__ hw,
                          const float* __restrict__ hin,
                          const int* __restrict__ rp, const int* __restrict__ col,
                          const float* __restrict__ dis,
                          const float* __restrict__ bc, const float* __restrict__ gn,
                          const float* __restrict__ bn, float* __restrict__ hout,
                          int residual) {
    const int lane = threadIdx.x & 31;
    const int n = blockIdx.x * 4 + (threadIdx.x >> 5);
    const float dn = dis[n];

    float4 sv = bf4(*(const uint2*)(hw + (size_t)n * 128 + lane * 4));
    ull a0 = pk2(dn * sv.x, dn * sv.y);
    ull a1 = pk2(dn * sv.z, dn * sv.w);

    int e = rp[n], end = rp[n + 1];
    for (; e + 4 <= end; e += 4) {
        int s0 = __ldg(&col[e]),     s1 = __ldg(&col[e + 1]);
        int s2 = __ldg(&col[e + 2]), s3 = __ldg(&col[e + 3]);
        float w0 = __ldg(&dis[s0]), w1 = __ldg(&dis[s1]);
        float w2 = __ldg(&dis[s2]), w3 = __ldg(&dis[s3]);
        uint2 u0 = *(const uint2*)(hw + (size_t)s0 * 128 + lane * 4);
        uint2 u1 = *(const uint2*)(hw + (size_t)s1 * 128 + lane * 4);
        uint2 u2 = *(const uint2*)(hw + (size_t)s2 * 128 + lane * 4);
        uint2 u3 = *(const uint2*)(hw + (size_t)s3 * 128 + lane * 4);
        float4 v0 = bf4(u0), v1 = bf4(u1), v2 = bf4(u2), v3 = bf4(u3);
        ull wp0 = pk2(w0, w0), wp1 = pk2(w1, w1), wp2 = pk2(w2, w2), wp3 = pk2(w3, w3);
        a0 = fma2(wp0, pk2(v0.x, v0.y), a0); a1 = fma2(wp0, pk2(v0.z, v0.w), a1);
        a0 = fma2(wp1, pk2(v1.x, v1.y), a0); a1 = fma2(wp1, pk2(v1.z, v1.w), a1);
        a0 = fma2(wp2, pk2(v2.x, v2.y), a0); a1 = fma2(wp2, pk2(v2.z, v2.w), a1);
        a0 = fma2(wp3, pk2(v3.x, v3.y), a0); a1 = fma2(wp3, pk2(v3.z, v3.w), a1);
    }
    for (; e < end; e++) {
        int s = __ldg(&col[e]);
        float w = __ldg(&dis[s]);
        float4 v0 = bf4(*(const uint2*)(hw + (size_t)s * 128 + lane * 4));
        ull wp = pk2(w, w);
        a0 = fma2(wp, pk2(v0.x, v0.y), a0);
        a1 = fma2(wp, pk2(v0.z, v0.w), a1);
    }

    float x0, x1, x2, x3;
    up2(a0, x0, x1); up2(a1, x2, x3);
    float4 bcv = *(const float4*)&bc[lane * 4];
    x0 = fmaf(dn, x0, bcv.x); x1 = fmaf(dn, x1, bcv.y);
    x2 = fmaf(dn, x2, bcv.z); x3 = fmaf(dn, x3, bcv.w);

    float s  = x0 + x1 + x2 + x3;
    float s2 = x0 * x0 + x1 * x1 + x2 * x2 + x3 * x3;
    #pragma unroll
    for (int o = 16; o > 0; o >>= 1) {
        s  += __shfl_xor_sync(0xffffffffu, s,  o);
        s2 += __shfl_xor_sync(0xffffffffu, s2, o);
    }
    float m   = s  * (1.0f / 128.0f);
    float var = s2 * (1.0f / 128.0f) - m * m;
    float r   = rsqrtf(var + 1e-5f);

    float4 gv = *(const float4*)&gn[lane * 4];
    float4 bv = *(const float4*)&bn[lane * 4];
    float y0 = fmaxf((x0 - m) * r * gv.x + bv.x, 0.0f);
    float y1 = fmaxf((x1 - m) * r * gv.y + bv.y, 0.0f);
    float y2 = fmaxf((x2 - m) * r * gv.z + bv.z, 0.0f);
    float y3 = fmaxf((x3 - m) * r * gv.w + bv.w, 0.0f);
    if (residual) {
        float4 hr = *(const float4*)(hin + (size_t)n * 128 + lane * 4);
        y0 += hr.x; y1 += hr.y; y2 += hr.z; y3 += hr.w;
    }
    *(float4*)(hout + (size_t)n * 128 + lane * 4) = make_float4(y0, y1, y2, y3);
}

// ---------------- attention: one block per (graph, head), packed f32x2 ----------------
__global__ __launch_bounds__(256) void k_attn(const float* __restrict__ qg,
                                              const float* __restrict__ kg,
                                              const float* __restrict__ vg,
                                              float* __restrict__ og) {
    __shared__ __align__(16) ull Ks[256][8];
    __shared__ __align__(16) ull Vs[256][8];
    int g = blockIdx.x >> 3;
    int h = blockIdx.x & 7;
    int t = threadIdx.x;
    const size_t base = (size_t)(g * NPG) * 128 + h * 16;

    {
        const ulonglong2* kp = (const ulonglong2*)(kg + base + (size_t)t * 128);
        const ulonglong2* vp = (const ulonglong2*)(vg + base + (size_t)t * 128);
        #pragma unroll
        for (int i = 0; i < 4; i++) {
            ulonglong2 kv = kp[i], vv = vp[i];
            Ks[t][2*i] = kv.x; Ks[t][2*i+1] = kv.y;
            Vs[t][2*i] = vv.x; Vs[t][2*i+1] = vv.y;
        }
    }
    ull qp[8];
    {
        const ulonglong2* qptr = (const ulonglong2*)(qg + base + (size_t)t * 128);
        #pragma unroll
        for (int i = 0; i < 4; i++) {
            ulonglong2 qv = qptr[i];
            qp[2*i] = qv.x; qp[2*i+1] = qv.y;
        }
    }
    __syncthreads();

    float l = 0.0f;
    ull acc[8];
    #pragma unroll
    for (int i = 0; i < 8; i++) acc[i] = 0ull;

    #pragma unroll 4
    for (int j = 0; j < 256; j++) {
        const ulonglong2* kr = (const ulonglong2*)&Ks[j][0];
        ulonglong2 k01 = kr[0], k23 = kr[1], k45 = kr[2], k67 = kr[3];
        ull sa = fma2(qp[0], k01.x, 0ull);
        ull sb = fma2(qp[1], k01.y, 0ull);
        sa = fma2(qp[2], k23.x, sa);
        sb = fma2(qp[3], k23.y, sb);
        sa = fma2(qp[4], k45.x, sa);
        sb = fma2(qp[5], k45.y, sb);
        sa = fma2(qp[6], k67.x, sa);
        sb = fma2(qp[7], k67.y, sb);
        sa = add2(sa, sb);
        float slo, shi;
        up2(sa, slo, shi);
        float s = (slo + shi) * 0.25f;
        float p = __expf(fminf(s, 60.0f));
        l += p;
        ull pp = pk2(p, p);
        const ulonglong2* vr = (const ulonglong2*)&Vs[j][0];
        ulonglong2 v01 = vr[0], v23 = vr[1], v45 = vr[2], v67 = vr[3];
        acc[0] = fma2(pp, v01.x, acc[0]);
        acc[1] = fma2(pp, v01.y, acc[1]);
        acc[2] = fma2(pp, v23.x, acc[2]);
        acc[3] = fma2(pp, v23.y, acc[3]);
        acc[4] = fma2(pp, v45.x, acc[4]);
        acc[5] = fma2(pp, v45.y, acc[5]);
        acc[6] = fma2(pp, v67.x, acc[6]);
        acc[7] = fma2(pp, v67.y, acc[7]);
    }
    float inv = 1.0f / l;
    float o[16];
    #pragma unroll
    for (int i = 0; i < 8; i++) {
        up2(acc[i], o[2*i], o[2*i+1]);
        o[2*i] *= inv; o[2*i+1] *= inv;
    }
    float4* op = (float4*)(og + base + (size_t)t * 128);
    op[0] = make_float4(o[0],  o[1],  o[2],  o[3]);
    op[1] = make_float4(o[4],  o[5],  o[6],  o[7]);
    op[2] = make_float4(o[8],  o[9],  o[10], o[11]);
    op[3] = make_float4(o[12], o[13], o[14], o[15]);
}

// ---------------- fused: LN(out_proj + residual) -> per-graph [mean,max,sum] pooling ----------------
__global__ __launch_bounds__(256) void k_ln_pool(const float* __restrict__ o2,
                          const float* __restrict__ hres,
                          const float* __restrict__ ga, const float* __restrict__ ba,
                          float* __restrict__ pooled) {
    __shared__ float ssum[8][128];
    __shared__ float smax[8][128];
    const int g = blockIdx.x;
    const int w = threadIdx.x >> 5, lane = threadIdx.x & 31;
    float4 gv = *(const float4*)&ga[lane * 4];
    float4 bv = *(const float4*)&ba[lane * 4];

    float4 ps = make_float4(0.f, 0.f, 0.f, 0.f);
    float4 pm = make_float4(-1e30f, -1e30f, -1e30f, -1e30f);

    #pragma unroll 2
    for (int i = 0; i < 32; i++) {
        size_t n = (size_t)g * NPG + w * 32 + i;
        float4 a = *(const float4*)(o2   + n * 128 + lane * 4);
        float4 b = *(const float4*)(hres + n * 128 + lane * 4);
        float x0 = a.x + b.x, x1 = a.y + b.y, x2 = a.z + b.z, x3 = a.w + b.w;
        float s  = x0 + x1 + x2 + x3;
        float s2 = x0*x0 + x1*x1 + x2*x2 + x3*x3;
        #pragma unroll
        for (int o = 16; o > 0; o >>= 1) {
            s  += __shfl_xor_sync(0xffffffffu, s,  o);
            s2 += __shfl_xor_sync(0xffffffffu, s2, o);
        }
        float m   = s  * (1.0f / 128.0f);
        float var = s2 * (1.0f / 128.0f) - m * m;
        float r   = rsqrtf(var + 1e-5f);
        float y0 = (x0 - m) * r * gv.x + bv.x;
        float y1 = (x1 - m) * r * gv.y + bv.y;
        float y2 = (x2 - m) * r * gv.z + bv.z;
        float y3 = (x3 - m) * r * gv.w + bv.w;
        ps.x += y0; ps.y += y1; ps.z += y2; ps.w += y3;
        pm.x = fmaxf(pm.x, y0); pm.y = fmaxf(pm.y, y1);
        pm.z = fmaxf(pm.z, y2); pm.w = fmaxf(pm.w, y3);
    }
    *(float4*)&ssum[w][lane * 4] = ps;
    *(float4*)&smax[w][lane * 4] = pm;
    __syncthreads();
    int f = threadIdx.x;
    if (f < 128) {
        float s = ssum[0][f], mx = smax[0][f];
        #pragma unroll
        for (int ww = 1; ww < 8; ww++) {
            s += ssum[ww][f];
            mx = fmaxf(mx, smax[ww][f]);
        }
        pooled[g * 384 + f]       = s * (1.0f / 256.0f);
        pooled[g * 384 + 128 + f] = mx;
        pooled[g * 384 + 256 + f] = s;
    }
}

// ---------------- classifier ----------------
__global__ void k_classifier(const float* __restrict__ pooled,
                             const float* __restrict__ W1, const float* __restrict__ b1,
                             const float* __restrict__ g1, const float* __restrict__ beta1,
                             const float* __restrict__ W2, const float* __restrict__ b2,
                             const float* __restrict__ W3, const float* __restrict__ b3,
                             float* __restrict__ out) {
    int g = blockIdx.x, f = threadIdx.x;
    __shared__ float ps[384];
    __shared__ float z1[128];
    __shared__ float z2[64];
    __shared__ float red[8];
    for (int i = f; i < 384; i += 128) ps[i] = pooled[g * 384 + i];
    __syncthreads();
    float acc = b1[f];
    for (int k = 0; k < 384; k++) acc = fmaf(ps[k], W1[k * 128 + f], acc);
    float y = fmaxf(block_ln_128(acc, g1[f], beta1[f], red), 0.0f);
    z1[f] = y;
    __syncthreads();
    if (f < 64) {
        float a = b2[f];
        #pragma unroll 8
        for (int k = 0; k < 128; k++) a = fmaf(z1[k], W2[k * 64 + f], a);
        z2[f] = fmaxf(a, 0.0f);
    }
    __syncthreads();
    if (f < 2) {
        float a = b3[f];
        #pragma unroll
        for (int k = 0; k < 64; k++) a = fmaf(z2[k], W3[k * 2 + f], a);
        out[g * 2 + f] = a;
    }
}

// ---------------- launch ----------------
extern "C" void kernel_launch(void* const* d_in, const int* in_sizes, int n_in,
                              void* d_out, int out_size) {
    const float* x     = (const float*)d_in[0];
    const int*   ei    = (const int*)  d_in[1];
    // d_in[2] = batch (unused; graphs are equal-sized)
    const float* W_in  = (const float*)d_in[3];
    const float* b_in  = (const float*)d_in[4];
    const float* g_in  = (const float*)d_in[5];
    const float* be_in = (const float*)d_in[6];
    const float* Wc    = (const float*)d_in[7];
    const float* bc    = (const float*)d_in[8];
    const float* gn    = (const float*)d_in[9];
    const float* bn    = (const float*)d_in[10];
    const float* Wq    = (const float*)d_in[11];
    const float* bq    = (const float*)d_in[12];
    const float* Wk    = (const float*)d_in[13];
    const float* bk    = (const float*)d_in[14];
    const float* Wv    = (const float*)d_in[15];
    const float* bv    = (const float*)d_in[16];
    const float* Wo    = (const float*)d_in[17];
    const float* bo    = (const float*)d_in[18];
    const float* ga    = (const float*)d_in[19];
    const float* ba    = (const float*)d_in[20];
    const float* W1    = (const float*)d_in[21];
    const float* b1    = (const float*)d_in[22];
    const float* g1    = (const float*)d_in[23];
    const float* beta1 = (const float*)d_in[24];
    const float* W2    = (const float*)d_in[25];
    const float* b2    = (const float*)d_in[26];
    const float* W3    = (const float*)d_in[27];
    const float* b3    = (const float*)d_in[28];
    float* out = (float*)d_out;

    const int* src = ei;
    const int* dst = ei + EE;

    float *p_h, *p_h2, *p_tmp, *p_q, *p_k, *p_v, *p_pool, *p_dis;
    ushort *p_hwbf;
    int *p_deg, *p_rp, *p_cur, *p_col;
    cudaGetSymbolAddress((void**)&p_h,    g_h);
    cudaGetSymbolAddress((void**)&p_h2,   g_h2);
    cudaGetSymbolAddress((void**)&p_tmp,  g_tmp);
    cudaGetSymbolAddress((void**)&p_q,    g_q);
    cudaGetSymbolAddress((void**)&p_k,    g_k);
    cudaGetSymbolAddress((void**)&p_v,    g_v);
    cudaGetSymbolAddress((void**)&p_hwbf, g_hwbf);
    cudaGetSymbolAddress((void**)&p_pool, g_pooled);
    cudaGetSymbolAddress((void**)&p_deg,  g_deg);
    cudaGetSymbolAddress((void**)&p_rp,   g_rp);
    cudaGetSymbolAddress((void**)&p_cur,  g_cur);
    cudaGetSymbolAddress((void**)&p_col,  g_col);
    cudaGetSymbolAddress((void**)&p_dis,  g_dis);

    // --- CSR build ---
    cudaMemsetAsync(p_deg, 0, NN * sizeof(int));
    k_hist<<<EE / 256, 256>>>(dst, p_deg);
    k_scan<<<1, 1024>>>(p_deg, p_rp, p_cur, p_dis);
    k_fill<<<EE / 256, 256>>>(src, dst, p_cur, p_col);

    // --- input projection ---
    k_input_proj<<<NN / 8, 256>>>(x, W_in, b_in, g_in, be_in, p_h);

    // --- 3 GCN layers (ping-pong h buffers) ---
    float* cur = p_h;
    float* nxt = p_h2;
    for (int i = 0; i < NLAYERS; i++) {
        k_gemm2<0, 0, 1><<<NN / 128, 256>>>(cur, Wc + i * HID * HID, nullptr, p_hwbf);
        k_gcn_agg<<<NN / 4, 128>>>(p_hwbf, cur, p_rp, p_col, p_dis,
                                   bc + i * HID, gn + i * HID, bn + i * HID, nxt, i > 0);
        float* t = cur; cur = nxt; nxt = t;
    }
    // after 3 layers: cur == p_h2

    // --- MHA ---
    {
        dim3 grid(NN / 128, 3);
        k_gemm_qkv<<<grid, 256>>>(cur, Wq, bq, p_q, Wk, bk, p_k, Wv, bv, p_v);
    }
    k_attn<<<GG * NH, 256>>>(p_q, p_k, p_v, p_tmp);
    k_gemm2<1, 1, 0><<<NN / 128, 256>>>(p_tmp, Wo, bo, p_q);   // p_q free, reuse

    // --- fused LN(residual) + pooling, then classifier ---
    k_ln_pool<<<GG, 256>>>(p_q, cur, ga, ba, p_pool);
    k_classifier<<<GG, 128>>>(p_pool, W1, b1, g1, beta1, W2, b2, W3, b3, out);
}

// round 5
// speedup vs baseline: 1.5848x; 1.1348x over previous
#include <cuda_runtime.h>
#include <math.h>

#define NN      32768      // nodes
#define GG      128        // graphs
#define NPG     256        // nodes per graph
#define HID     128
#define NH      8
#define DH      16
#define EE      1048576    // edges
#define NLAYERS 3
#define SPADF   68         // fp32 words per smem tile row (BK=64 + pad 4)

typedef unsigned long long ull;
typedef unsigned int uint;
typedef unsigned short ushort;

// ---------------- packed f32x2 helpers ----------------
__device__ __forceinline__ ull pk2(float lo, float hi) {
    ull r; asm("mov.b64 %0,{%1,%2};" : "=l"(r) : "f"(lo), "f"(hi)); return r;
}
__device__ __forceinline__ void up2(ull v, float& lo, float& hi) {
    asm("mov.b64 {%0,%1},%2;" : "=f"(lo), "=f"(hi) : "l"(v));
}
__device__ __forceinline__ ull fma2(ull a, ull b, ull c) {
    ull d; asm("fma.rn.f32x2 %0,%1,%2,%3;" : "=l"(d) : "l"(a), "l"(b), "l"(c)); return d;
}
__device__ __forceinline__ ull add2(ull a, ull b) {
    ull d; asm("add.rn.f32x2 %0,%1,%2;" : "=l"(d) : "l"(a), "l"(b)); return d;
}
// pack 2 fp32 -> bf16x2 (lo in low half)
__device__ __forceinline__ uint bf2(float lo, float hi) {
    uint r; asm("cvt.rn.bf16x2.f32 %0,%1,%2;" : "=r"(r) : "f"(hi), "f"(lo)); return r;
}
// unpack bf16x2 word -> 2 fp32
__device__ __forceinline__ float4 bf4(uint2 u) {
    float4 r;
    r.x = __uint_as_float(u.x << 16);
    r.y = __uint_as_float(u.x & 0xffff0000u);
    r.z = __uint_as_float(u.y << 16);
    r.w = __uint_as_float(u.y & 0xffff0000u);
    return r;
}
// fp32 -> tf32 bits
__device__ __forceinline__ uint tf32(float x) {
    uint r; asm("cvt.rna.tf32.f32 %0,%1;" : "=r"(r) : "f"(x)); return r;
}
__device__ __forceinline__ void mma1688(float* c, uint a0, uint a1, uint a2, uint a3,
                                        uint b0, uint b1) {
    asm volatile("mma.sync.aligned.m16n8k8.row.col.f32.tf32.tf32.f32 "
        "{%0,%1,%2,%3},{%4,%5,%6,%7},{%8,%9},{%0,%1,%2,%3};"
        : "+f"(c[0]), "+f"(c[1]), "+f"(c[2]), "+f"(c[3])
        : "r"(a0), "r"(a1), "r"(a2), "r"(a3), "r"(b0), "r"(b1));
}

// ---------------- scratch (device globals; no runtime alloc allowed) ----------------
__device__ float  g_h   [NN * HID];
__device__ float  g_h2  [NN * HID];
__device__ float  g_tmp [NN * HID];
__device__ float  g_q   [NN * HID];
__device__ float  g_k   [NN * HID];
__device__ float  g_v   [NN * HID];
__device__ ushort g_hwbf[NN * HID];     // bf16 GCN-GEMM output for aggregation
__device__ float  g_pooled[GG * 3 * HID];
__device__ int    g_deg[NN];
__device__ int    g_rp [NN + 1];
__device__ int    g_cur[NN];
__device__ int    g_col[EE];
__device__ float  g_dis[NN];

// ---------------- block LN (128 threads) ----------------
__device__ __forceinline__ float block_ln_128(float v, float gamma, float beta, float* sh) {
    float s = v, s2 = v * v;
    #pragma unroll
    for (int o = 16; o > 0; o >>= 1) {
        s  += __shfl_down_sync(0xffffffffu, s,  o);
        s2 += __shfl_down_sync(0xffffffffu, s2, o);
    }
    int w = threadIdx.x >> 5, l = threadIdx.x & 31;
    if (l == 0) { sh[w] = s; sh[4 + w] = s2; }
    __syncthreads();
    float ts  = sh[0] + sh[1] + sh[2] + sh[3];
    float ts2 = sh[4] + sh[5] + sh[6] + sh[7];
    float m   = ts  * (1.0f / 128.0f);
    float var = ts2 * (1.0f / 128.0f) - m * m;
    float r   = rsqrtf(var + 1e-5f);
    __syncthreads();
    return (v - m) * r * gamma + beta;
}

// ---------------- CSR build ----------------
__global__ void k_hist(const int* __restrict__ dst, int* __restrict__ deg) {
    int e = blockIdx.x * blockDim.x + threadIdx.x;
    if (e < EE) atomicAdd(&deg[dst[e]], 1);
}

__global__ void k_scan(const int* __restrict__ deg, int* __restrict__ rp,
                       int* __restrict__ cur, float* __restrict__ dis) {
    __shared__ int part[1024];
    int tid = threadIdx.x;            // 1024 threads
    int base = tid * 32;
    int v[32];
    int s = 0;
    #pragma unroll
    for (int i = 0; i < 32; i++) { v[i] = deg[base + i]; s += v[i]; }
    part[tid] = s;
    __syncthreads();
    for (int off = 1; off < 1024; off <<= 1) {
        int t = (tid >= off) ? part[tid - off] : 0;
        __syncthreads();
        part[tid] += t;
        __syncthreads();
    }
    int run = part[tid] - s;          // exclusive prefix
    #pragma unroll
    for (int i = 0; i < 32; i++) {
        rp[base + i]  = run;
        cur[base + i] = run;
        dis[base + i] = rsqrtf((float)v[i] + 1.0f);  // +1 self loop
        run += v[i];
    }
    if (tid == 1023) rp[NN] = run;
}

__global__ void k_fill(const int* __restrict__ src, const int* __restrict__ dst,
                       int* __restrict__ cur, int* __restrict__ col) {
    int e = blockIdx.x * blockDim.x + threadIdx.x;
    if (e < EE) {
        int d = dst[e];
        int pos = atomicAdd(&cur[d], 1);
        col[pos] = src[e];
    }
}

// ---------------- input projection: relu(ln(x @ W_in + b_in)) ----------------
// warp processes 8 nodes; W cached in registers; x loaded coalesced + shuffled.
__global__ __launch_bounds__(256) void k_input_proj(const float* __restrict__ x,
                             const float* __restrict__ W,
                             const float* __restrict__ b, const float* __restrict__ g,
                             const float* __restrict__ be, float* __restrict__ out) {
    const int lane = threadIdx.x & 31;
    const int n0 = (blockIdx.x * 8 + (threadIdx.x >> 5)) * 8;   // 8 nodes per warp
    float4 w[15];
    #pragma unroll
    for (int k = 0; k < 15; k++) w[k] = *(const float4*)&W[k * 128 + lane * 4];
    const float4 bb = *(const float4*)&b[lane * 4];
    const float4 gv = *(const float4*)&g[lane * 4];
    const float4 bv = *(const float4*)&be[lane * 4];
    // 8 nodes * 15 feats = 120 floats, coalesced
    float4 xv = make_float4(0.f, 0.f, 0.f, 0.f);
    if (lane < 30) xv = *(const float4*)&x[n0 * 15 + lane * 4];

    #pragma unroll
    for (int i = 0; i < 8; i++) {
        float4 acc = bb;
        #pragma unroll
        for (int k = 0; k < 15; k++) {
            const int e = i * 15 + k;
            const int srcLane = e >> 2, comp = e & 3;
            float xe = (comp == 0) ? xv.x : (comp == 1) ? xv.y : (comp == 2) ? xv.z : xv.w;
            float xk = __shfl_sync(0xffffffffu, xe, srcLane);
            acc.x = fmaf(xk, w[k].x, acc.x); acc.y = fmaf(xk, w[k].y, acc.y);
            acc.z = fmaf(xk, w[k].z, acc.z); acc.w = fmaf(xk, w[k].w, acc.w);
        }
        float s  = acc.x + acc.y + acc.z + acc.w;
        float s2 = acc.x*acc.x + acc.y*acc.y + acc.z*acc.z + acc.w*acc.w;
        #pragma unroll
        for (int o = 16; o > 0; o >>= 1) {
            s  += __shfl_xor_sync(0xffffffffu, s,  o);
            s2 += __shfl_xor_sync(0xffffffffu, s2, o);
        }
        float m   = s * (1.0f / 128.0f);
        float var = s2 * (1.0f / 128.0f) - m * m;
        float r   = rsqrtf(var + 1e-5f);
        float4 y;
        y.x = fmaxf((acc.x - m) * r * gv.x + bv.x, 0.0f);
        y.y = fmaxf((acc.y - m) * r * gv.y + bv.y, 0.0f);
        y.z = fmaxf((acc.z - m) * r * gv.z + bv.z, 0.0f);
        y.w = fmaxf((acc.w - m) * r * gv.w + bv.w, 0.0f);
        *(float4*)(out + (size_t)(n0 + i) * 128 + lane * 4) = y;
    }
}

// ---------------- tf32 tensor-core GEMM: C[M,128] = A[M,128] @ op(B) (+bias) ----------------
// BM=128, BN=128, BK=64 (2 k-tiles); 256 threads = 8 warps (2m x 4n), warp tile 64x32.
// Inputs converted to tf32 in smem; mma.sync m16n8k8, fp32 accumulate.
// Smem tiles stored k-fastest: As[m][k], Bs[f][k] (TRANSB=0 transposes B during load).
template <int TRANSB, int BIAS, int BF16OUT>
__device__ __forceinline__ void tgemm_dev(uint* sm, const float* __restrict__ A,
                                          const float* __restrict__ B,
                                          const float* __restrict__ bias,
                                          void* __restrict__ Cv) {
    uint* As = sm;                   // [128][SPADF]
    uint* Bs = sm + 128 * SPADF;     // [128][SPADF]
    const int t = threadIdx.x;
    const int lane = t & 31, warp = t >> 5;
    const int row0 = blockIdx.x * 128;
    const int m0 = (warp >> 2) * 64;
    const int n0 = (warp & 3) * 32;
    const int gid = lane >> 2, tg = lane & 3;

    float acc[4][4][4];
    #pragma unroll
    for (int mi = 0; mi < 4; mi++)
        #pragma unroll
        for (int ni = 0; ni < 4; ni++)
            #pragma unroll
            for (int q = 0; q < 4; q++) acc[mi][ni][q] = 0.0f;

    #pragma unroll
    for (int kt = 0; kt < 2; kt++) {
        const int k0g = kt * 64;
        // A tile: 128 rows x 64 k -> 8 float4 per thread
        #pragma unroll
        for (int i = 0; i < 8; i++) {
            int idx = i * 256 + t;
            int r = idx >> 4, c4 = (idx & 15) * 4;
            float4 v = *(const float4*)&A[(size_t)(row0 + r) * 128 + k0g + c4];
            *(uint4*)&As[r * SPADF + c4] =
                make_uint4(tf32(v.x), tf32(v.y), tf32(v.z), tf32(v.w));
        }
        // B tile
        if (TRANSB) {   // B[f][k]: same pattern as A
            #pragma unroll
            for (int i = 0; i < 8; i++) {
                int idx = i * 256 + t;
                int r = idx >> 4, c4 = (idx & 15) * 4;
                float4 v = *(const float4*)&B[(size_t)r * 128 + k0g + c4];
                *(uint4*)&Bs[r * SPADF + c4] =
                    make_uint4(tf32(v.x), tf32(v.y), tf32(v.z), tf32(v.w));
            }
        } else {        // B[k][f] -> Bs[f][k] (transpose)
            #pragma unroll
            for (int i = 0; i < 8; i++) {
                int idx = i * 256 + t;
                int r = idx >> 5, f0 = (idx & 31) * 4;   // r: k-row 0..63
                float4 v = *(const float4*)&B[(size_t)(k0g + r) * 128 + f0];
                Bs[(f0 + 0) * SPADF + r] = tf32(v.x);
                Bs[(f0 + 1) * SPADF + r] = tf32(v.y);
                Bs[(f0 + 2) * SPADF + r] = tf32(v.z);
                Bs[(f0 + 3) * SPADF + r] = tf32(v.w);
            }
        }
        __syncthreads();
        #pragma unroll
        for (int ks = 0; ks < 8; ks++) {
            const int kb = ks * 8;
            uint af[4][4];
            #pragma unroll
            for (int mi = 0; mi < 4; mi++) {
                const uint* ar0 = &As[(m0 + mi * 16 + gid) * SPADF + kb + tg];
                const uint* ar1 = &As[(m0 + mi * 16 + gid + 8) * SPADF + kb + tg];
                af[mi][0] = ar0[0];
                af[mi][1] = ar1[0];
                af[mi][2] = ar0[4];
                af[mi][3] = ar1[4];
            }
            uint bfr[4][2];
            #pragma unroll
            for (int ni = 0; ni < 4; ni++) {
                const uint* br = &Bs[(n0 + ni * 8 + gid) * SPADF + kb + tg];
                bfr[ni][0] = br[0];
                bfr[ni][1] = br[4];
            }
            #pragma unroll
            for (int mi = 0; mi < 4; mi++)
                #pragma unroll
                for (int ni = 0; ni < 4; ni++)
                    mma1688(acc[mi][ni], af[mi][0], af[mi][1], af[mi][2], af[mi][3],
                            bfr[ni][0], bfr[ni][1]);
        }
        __syncthreads();
    }

    // epilogue
    float2 bb[4];
    #pragma unroll
    for (int ni = 0; ni < 4; ni++) {
        if (BIAS) bb[ni] = *(const float2*)&bias[n0 + ni * 8 + tg * 2];
        else      bb[ni] = make_float2(0.f, 0.f);
    }
    #pragma unroll
    for (int mi = 0; mi < 4; mi++) {
        int r = row0 + m0 + mi * 16 + gid;
        #pragma unroll
        for (int ni = 0; ni < 4; ni++) {
            int c = n0 + ni * 8 + tg * 2;
            float v0 = acc[mi][ni][0] + bb[ni].x;
            float v1 = acc[mi][ni][1] + bb[ni].y;
            float v2 = acc[mi][ni][2] + bb[ni].x;
            float v3 = acc[mi][ni][3] + bb[ni].y;
            if (BF16OUT) {
                ushort* Cb = (ushort*)Cv;
                *(uint*)(Cb + (size_t)r * 128 + c)       = bf2(v0, v1);
                *(uint*)(Cb + (size_t)(r + 8) * 128 + c) = bf2(v2, v3);
            } else {
                float* C = (float*)Cv;
                *(float2*)&C[(size_t)r * 128 + c]       = make_float2(v0, v1);
                *(float2*)&C[(size_t)(r + 8) * 128 + c] = make_float2(v2, v3);
            }
        }
    }
}

template <int TRANSB, int BIAS, int BF16OUT>
__global__ __launch_bounds__(256, 2) void k_tgemm(const float* __restrict__ A,
                                                  const float* __restrict__ B,
                                                  const float* __restrict__ bias,
                                                  void* __restrict__ C) {
    extern __shared__ uint smx[];
    tgemm_dev<TRANSB, BIAS, BF16OUT>(smx, A, B, bias, C);
}

// fused QKV: grid.y in {0,1,2} selects weight/bias/output
__global__ __launch_bounds__(256, 2) void k_tgemm_qkv(const float* __restrict__ A,
    const float* __restrict__ Wq, const float* __restrict__ bq, float* __restrict__ q,
    const float* __restrict__ Wk, const float* __restrict__ bk, float* __restrict__ k,
    const float* __restrict__ Wv, const float* __restrict__ bv, float* __restrict__ v) {
    extern __shared__ uint smx[];
    int s = blockIdx.y;
    const float* B  = (s == 0) ? Wq : (s == 1) ? Wk : Wv;
    const float* bi = (s == 0) ? bq : (s == 1) ? bk : bv;
    float*       C  = (s == 0) ? q  : (s == 1) ? k  : v;
    tgemm_dev<1, 1, 0>(smx, A, B, bi, C);
}

// ---------------- GCN aggregate (bf16 rows) + bias + LN + relu + residual ----------------
__global__ __launch_bounds__(128) void k_gcn_agg(const ushort* __restrict__ hw,
                          const float* __restrict__ hin,
                          const int* __restrict__ rp, const int* __restrict__ col,
                          const float* __restrict__ dis,
                          const float* __restrict__ bc, const float* __restrict__ gn,
                          const float* __restrict__ bn, float* __restrict__ hout,
                          int residual) {
    const int lane = threadIdx.x & 31;
    const int n = blockIdx.x * 4 + (threadIdx.x >> 5);
    const float dn = dis[n];

    float4 sv = bf4(*(const uint2*)(hw + (size_t)n * 128 + lane * 4));
    ull a0 = pk2(dn * sv.x, dn * sv.y);
    ull a1 = pk2(dn * sv.z, dn * sv.w);

    int e = rp[n], end = rp[n + 1];
    for (; e + 4 <= end; e += 4) {
        int s0 = __ldg(&col[e]),     s1 = __ldg(&col[e + 1]);
        int s2 = __ldg(&col[e + 2]), s3 = __ldg(&col[e + 3]);
        float w0 = __ldg(&dis[s0]), w1 = __ldg(&dis[s1]);
        float w2 = __ldg(&dis[s2]), w3 = __ldg(&dis[s3]);
        uint2 u0 = *(const uint2*)(hw + (size_t)s0 * 128 + lane * 4);
        uint2 u1 = *(const uint2*)(hw + (size_t)s1 * 128 + lane * 4);
        uint2 u2 = *(const uint2*)(hw + (size_t)s2 * 128 + lane * 4);
        uint2 u3 = *(const uint2*)(hw + (size_t)s3 * 128 + lane * 4);
        float4 v0 = bf4(u0), v1 = bf4(u1), v2 = bf4(u2), v3 = bf4(u3);
        ull wp0 = pk2(w0, w0), wp1 = pk2(w1, w1), wp2 = pk2(w2, w2), wp3 = pk2(w3, w3);
        a0 = fma2(wp0, pk2(v0.x, v0.y), a0); a1 = fma2(wp0, pk2(v0.z, v0.w), a1);
        a0 = fma2(wp1, pk2(v1.x, v1.y), a0); a1 = fma2(wp1, pk2(v1.z, v1.w), a1);
        a0 = fma2(wp2, pk2(v2.x, v2.y), a0); a1 = fma2(wp2, pk2(v2.z, v2.w), a1);
        a0 = fma2(wp3, pk2(v3.x, v3.y), a0); a1 = fma2(wp3, pk2(v3.z, v3.w), a1);
    }
    for (; e < end; e++) {
        int s = __ldg(&col[e]);
        float w = __ldg(&dis[s]);
        float4 v0 = bf4(*(const uint2*)(hw + (size_t)s * 128 + lane * 4));
        ull wp = pk2(w, w);
        a0 = fma2(wp, pk2(v0.x, v0.y), a0);
        a1 = fma2(wp, pk2(v0.z, v0.w), a1);
    }

    float x0, x1, x2, x3;
    up2(a0, x0, x1); up2(a1, x2, x3);
    float4 bcv = *(const float4*)&bc[lane * 4];
    x0 = fmaf(dn, x0, bcv.x); x1 = fmaf(dn, x1, bcv.y);
    x2 = fmaf(dn, x2, bcv.z); x3 = fmaf(dn, x3, bcv.w);

    float s  = x0 + x1 + x2 + x3;
    float s2 = x0 * x0 + x1 * x1 + x2 * x2 + x3 * x3;
    #pragma unroll
    for (int o = 16; o > 0; o >>= 1) {
        s  += __shfl_xor_sync(0xffffffffu, s,  o);
        s2 += __shfl_xor_sync(0xffffffffu, s2, o);
    }
    float m   = s  * (1.0f / 128.0f);
    float var = s2 * (1.0f / 128.0f) - m * m;
    float r   = rsqrtf(var + 1e-5f);

    float4 gv = *(const float4*)&gn[lane * 4];
    float4 bv = *(const float4*)&bn[lane * 4];
    float y0 = fmaxf((x0 - m) * r * gv.x + bv.x, 0.0f);
    float y1 = fmaxf((x1 - m) * r * gv.y + bv.y, 0.0f);
    float y2 = fmaxf((x2 - m) * r * gv.z + bv.z, 0.0f);
    float y3 = fmaxf((x3 - m) * r * gv.w + bv.w, 0.0f);
    if (residual) {
        float4 hr = *(const float4*)(hin + (size_t)n * 128 + lane * 4);
        y0 += hr.x; y1 += hr.y; y2 += hr.z; y3 += hr.w;
    }
    *(float4*)(hout + (size_t)n * 128 + lane * 4) = make_float4(y0, y1, y2, y3);
}

// ---------------- attention: one block per (graph, head), packed f32x2 ----------------
__global__ __launch_bounds__(256) void k_attn(const float* __restrict__ qg,
                                              const float* __restrict__ kg,
                                              const float* __restrict__ vg,
                                              float* __restrict__ og) {
    __shared__ __align__(16) ull Ks[256][8];
    __shared__ __align__(16) ull Vs[256][8];
    int g = blockIdx.x >> 3;
    int h = blockIdx.x & 7;
    int t = threadIdx.x;
    const size_t base = (size_t)(g * NPG) * 128 + h * 16;

    {
        const ulonglong2* kp = (const ulonglong2*)(kg + base + (size_t)t * 128);
        const ulonglong2* vp = (const ulonglong2*)(vg + base + (size_t)t * 128);
        #pragma unroll
        for (int i = 0; i < 4; i++) {
            ulonglong2 kv = kp[i], vv = vp[i];
            Ks[t][2*i] = kv.x; Ks[t][2*i+1] = kv.y;
            Vs[t][2*i] = vv.x; Vs[t][2*i+1] = vv.y;
        }
    }
    ull qp[8];
    {
        const ulonglong2* qptr = (const ulonglong2*)(qg + base + (size_t)t * 128);
        #pragma unroll
        for (int i = 0; i < 4; i++) {
            ulonglong2 qv = qptr[i];
            qp[2*i] = qv.x; qp[2*i+1] = qv.y;
        }
    }
    __syncthreads();

    float l = 0.0f;
    ull acc[8];
    #pragma unroll
    for (int i = 0; i < 8; i++) acc[i] = 0ull;

    #pragma unroll 4
    for (int j = 0; j < 256; j++) {
        const ulonglong2* kr = (const ulonglong2*)&Ks[j][0];
        ulonglong2 k01 = kr[0], k23 = kr[1], k45 = kr[2], k67 = kr[3];
        ull sa = fma2(qp[0], k01.x, 0ull);
        ull sb = fma2(qp[1], k01.y, 0ull);
        sa = fma2(qp[2], k23.x, sa);
        sb = fma2(qp[3], k23.y, sb);
        sa = fma2(qp[4], k45.x, sa);
        sb = fma2(qp[5], k45.y, sb);
        sa = fma2(qp[6], k67.x, sa);
        sb = fma2(qp[7], k67.y, sb);
        sa = add2(sa, sb);
        float slo, shi;
        up2(sa, slo, shi);
        float s = (slo + shi) * 0.25f;
        float p = __expf(fminf(s, 60.0f));
        l += p;
        ull pp = pk2(p, p);
        const ulonglong2* vr = (const ulonglong2*)&Vs[j][0];
        ulonglong2 v01 = vr[0], v23 = vr[1], v45 = vr[2], v67 = vr[3];
        acc[0] = fma2(pp, v01.x, acc[0]);
        acc[1] = fma2(pp, v01.y, acc[1]);
        acc[2] = fma2(pp, v23.x, acc[2]);
        acc[3] = fma2(pp, v23.y, acc[3]);
        acc[4] = fma2(pp, v45.x, acc[4]);
        acc[5] = fma2(pp, v45.y, acc[5]);
        acc[6] = fma2(pp, v67.x, acc[6]);
        acc[7] = fma2(pp, v67.y, acc[7]);
    }
    float inv = 1.0f / l;
    float o[16];
    #pragma unroll
    for (int i = 0; i < 8; i++) {
        up2(acc[i], o[2*i], o[2*i+1]);
        o[2*i] *= inv; o[2*i+1] *= inv;
    }
    float4* op = (float4*)(og + base + (size_t)t * 128);
    op[0] = make_float4(o[0],  o[1],  o[2],  o[3]);
    op[1] = make_float4(o[4],  o[5],  o[6],  o[7]);
    op[2] = make_float4(o[8],  o[9],  o[10], o[11]);
    op[3] = make_float4(o[12], o[13], o[14], o[15]);
}

// ---------------- fused: LN(out_proj + residual) -> per-graph [mean,max,sum] pooling ----------------
__global__ __launch_bounds__(256) void k_ln_pool(const float* __restrict__ o2,
                          const float* __restrict__ hres,
                          const float* __restrict__ ga, const float* __restrict__ ba,
                          float* __restrict__ pooled) {
    __shared__ float ssum[8][128];
    __shared__ float smax[8][128];
    const int g = blockIdx.x;
    const int w = threadIdx.x >> 5, lane = threadIdx.x & 31;
    float4 gv = *(const float4*)&ga[lane * 4];
    float4 bv = *(const float4*)&ba[lane * 4];

    float4 ps = make_float4(0.f, 0.f, 0.f, 0.f);
    float4 pm = make_float4(-1e30f, -1e30f, -1e30f, -1e30f);

    #pragma unroll 2
    for (int i = 0; i < 32; i++) {
        size_t n = (size_t)g * NPG + w * 32 + i;
        float4 a = *(const float4*)(o2   + n * 128 + lane * 4);
        float4 b = *(const float4*)(hres + n * 128 + lane * 4);
        float x0 = a.x + b.x, x1 = a.y + b.y, x2 = a.z + b.z, x3 = a.w + b.w;
        float s  = x0 + x1 + x2 + x3;
        float s2 = x0*x0 + x1*x1 + x2*x2 + x3*x3;
        #pragma unroll
        for (int o = 16; o > 0; o >>= 1) {
            s  += __shfl_xor_sync(0xffffffffu, s,  o);
            s2 += __shfl_xor_sync(0xffffffffu, s2, o);
        }
        float m   = s  * (1.0f / 128.0f);
        float var = s2 * (1.0f / 128.0f) - m * m;
        float r   = rsqrtf(var + 1e-5f);
        float y0 = (x0 - m) * r * gv.x + bv.x;
        float y1 = (x1 - m) * r * gv.y + bv.y;
        float y2 = (x2 - m) * r * gv.z + bv.z;
        float y3 = (x3 - m) * r * gv.w + bv.w;
        ps.x += y0; ps.y += y1; ps.z += y2; ps.w += y3;
        pm.x = fmaxf(pm.x, y0); pm.y = fmaxf(pm.y, y1);
        pm.z = fmaxf(pm.z, y2); pm.w = fmaxf(pm.w, y3);
    }
    *(float4*)&ssum[w][lane * 4] = ps;
    *(float4*)&smax[w][lane * 4] = pm;
    __syncthreads();
    int f = threadIdx.x;
    if (f < 128) {
        float s = ssum[0][f], mx = smax[0][f];
        #pragma unroll
        for (int ww = 1; ww < 8; ww++) {
            s += ssum[ww][f];
            mx = fmaxf(mx, smax[ww][f]);
        }
        pooled[g * 384 + f]       = s * (1.0f / 256.0f);
        pooled[g * 384 + 128 + f] = mx;
        pooled[g * 384 + 256 + f] = s;
    }
}

// ---------------- classifier ----------------
__global__ void k_classifier(const float* __restrict__ pooled,
                             const float* __restrict__ W1, const float* __restrict__ b1,
                             const float* __restrict__ g1, const float* __restrict__ beta1,
                             const float* __restrict__ W2, const float* __restrict__ b2,
                             const float* __restrict__ W3, const float* __restrict__ b3,
                             float* __restrict__ out) {
    int g = blockIdx.x, f = threadIdx.x;
    __shared__ float ps[384];
    __shared__ float z1[128];
    __shared__ float z2[64];
    __shared__ float red[8];
    for (int i = f; i < 384; i += 128) ps[i] = pooled[g * 384 + i];
    __syncthreads();
    float acc = b1[f];
    for (int k = 0; k < 384; k++) acc = fmaf(ps[k], W1[k * 128 + f], acc);
    float y = fmaxf(block_ln_128(acc, g1[f], beta1[f], red), 0.0f);
    z1[f] = y;
    __syncthreads();
    if (f < 64) {
        float a = b2[f];
        #pragma unroll 8
        for (int k = 0; k < 128; k++) a = fmaf(z1[k], W2[k * 64 + f], a);
        z2[f] = fmaxf(a, 0.0f);
    }
    __syncthreads();
    if (f < 2) {
        float a = b3[f];
        #pragma unroll
        for (int k = 0; k < 64; k++) a = fmaf(z2[k], W3[k * 2 + f], a);
        out[g * 2 + f] = a;
    }
}

// ---------------- launch ----------------
extern "C" void kernel_launch(void* const* d_in, const int* in_sizes, int n_in,
                              void* d_out, int out_size) {
    const float* x     = (const float*)d_in[0];
    const int*   ei    = (const int*)  d_in[1];
    // d_in[2] = batch (unused; graphs are equal-sized)
    const float* W_in  = (const float*)d_in[3];
    const float* b_in  = (const float*)d_in[4];
    const float* g_in  = (const float*)d_in[5];
    const float* be_in = (const float*)d_in[6];
    const float* Wc    = (const float*)d_in[7];
    const float* bc    = (const float*)d_in[8];
    const float* gn    = (const float*)d_in[9];
    const float* bn    = (const float*)d_in[10];
    const float* Wq    = (const float*)d_in[11];
    const float* bq    = (const float*)d_in[12];
    const float* Wk    = (const float*)d_in[13];
    const float* bk    = (const float*)d_in[14];
    const float* Wv    = (const float*)d_in[15];
    const float* bv    = (const float*)d_in[16];
    const float* Wo    = (const float*)d_in[17];
    const float* bo    = (const float*)d_in[18];
    const float* ga    = (const float*)d_in[19];
    const float* ba    = (const float*)d_in[20];
    const float* W1    = (const float*)d_in[21];
    const float* b1    = (const float*)d_in[22];
    const float* g1    = (const float*)d_in[23];
    const float* beta1 = (const float*)d_in[24];
    const float* W2    = (const float*)d_in[25];
    const float* b2    = (const float*)d_in[26];
    const float* W3    = (const float*)d_in[27];
    const float* b3    = (const float*)d_in[28];
    float* out = (float*)d_out;

    const int* src = ei;
    const int* dst = ei + EE;

    float *p_h, *p_h2, *p_tmp, *p_q, *p_k, *p_v, *p_pool, *p_dis;
    ushort *p_hwbf;
    int *p_deg, *p_rp, *p_cur, *p_col;
    cudaGetSymbolAddress((void**)&p_h,    g_h);
    cudaGetSymbolAddress((void**)&p_h2,   g_h2);
    cudaGetSymbolAddress((void**)&p_tmp,  g_tmp);
    cudaGetSymbolAddress((void**)&p_q,    g_q);
    cudaGetSymbolAddress((void**)&p_k,    g_k);
    cudaGetSymbolAddress((void**)&p_v,    g_v);
    cudaGetSymbolAddress((void**)&p_hwbf, g_hwbf);
    cudaGetSymbolAddress((void**)&p_pool, g_pooled);
    cudaGetSymbolAddress((void**)&p_deg,  g_deg);
    cudaGetSymbolAddress((void**)&p_rp,   g_rp);
    cudaGetSymbolAddress((void**)&p_cur,  g_cur);
    cudaGetSymbolAddress((void**)&p_col,  g_col);
    cudaGetSymbolAddress((void**)&p_dis,  g_dis);

    const int HS = 2 * 128 * SPADF * sizeof(uint);   // 69632 B dynamic smem
    cudaFuncSetAttribute(k_tgemm<0, 0, 1>, cudaFuncAttributeMaxDynamicSharedMemorySize, HS);
    cudaFuncSetAttribute(k_tgemm<1, 1, 0>, cudaFuncAttributeMaxDynamicSharedMemorySize, HS);
    cudaFuncSetAttribute(k_tgemm_qkv,      cudaFuncAttributeMaxDynamicSharedMemorySize, HS);

    // --- input projection first (independent of CSR) ---
    cudaMemsetAsync(p_deg, 0, NN * sizeof(int));
    k_input_proj<<<NN / 64, 256>>>(x, W_in, b_in, g_in, be_in, p_h);

    // --- CSR build ---
    k_hist<<<EE / 256, 256>>>(dst, p_deg);
    k_scan<<<1, 1024>>>(p_deg, p_rp, p_cur, p_dis);
    k_fill<<<EE / 256, 256>>>(src, dst, p_cur, p_col);

    // --- 3 GCN layers (ping-pong h buffers) ---
    float* cur = p_h;
    float* nxt = p_h2;
    for (int i = 0; i < NLAYERS; i++) {
        k_tgemm<0, 0, 1><<<NN / 128, 256, HS>>>(cur, Wc + i * HID * HID, nullptr, p_hwbf);
        k_gcn_agg<<<NN / 4, 128>>>(p_hwbf, cur, p_rp, p_col, p_dis,
                                   bc + i * HID, gn + i * HID, bn + i * HID, nxt, i > 0);
        float* t = cur; cur = nxt; nxt = t;
    }
    // after 3 layers: cur == p_h2

    // --- MHA ---
    {
        dim3 grid(NN / 128, 3);
        k_tgemm_qkv<<<grid, 256, HS>>>(cur, Wq, bq, p_q, Wk, bk, p_k, Wv, bv, p_v);
    }
    k_attn<<<GG * NH, 256>>>(p_q, p_k, p_v, p_tmp);
    k_tgemm<1, 1, 0><<<NN / 128, 256, HS>>>(p_tmp, Wo, bo, p_q);   // p_q free, reuse

    // --- fused LN(residual) + pooling, then classifier ---
    k_ln_pool<<<GG, 256>>>(p_q, cur, ga, ba, p_pool);
    k_classifier<<<GG, 128>>>(p_pool, W1, b1, g1, beta1, W2, b2, W3, b3, out);
}